// round 1
// baseline (speedup 1.0000x reference)
#include <cuda_runtime.h>
#include <cuda_bf16.h>
#include <math.h>

// ---------------- problem constants ----------------
#define Tn 128
#define Bn 32
#define En 4096
#define Hn 512
#define FOURH 2048
#define TB 4096          // T*B
#define Kc 20
#define START_TAG 18
#define STOP_TAG 19

// ---------------- scratch (device globals; allocation-free) ----------------
__device__ float g_xn[(size_t)TB * En];          // 64 MB
__device__ float g_xgf[(size_t)TB * FOURH];      // 32 MB
__device__ float g_xgb[(size_t)TB * FOURH];      // 32 MB
__device__ float g_hf[(size_t)TB * Hn];          // 8 MB
__device__ float g_hb[(size_t)TB * Hn];          // 8 MB
__device__ float g_hping[2][2][Bn * Hn];         // ping-pong h per direction
__device__ float g_feats[(size_t)Bn * Tn * Kc];

__device__ unsigned g_bar_count = 0;
__device__ volatile unsigned g_bar_gen = 0;

// ---------------- grid barrier (all CTAs co-resident by construction) ------
__device__ __forceinline__ void grid_barrier(unsigned nb) {
    __syncthreads();
    if (threadIdx.x == 0) {
        unsigned gen = g_bar_gen;
        __threadfence();
        if (atomicAdd(&g_bar_count, 1u) == nb - 1u) {
            g_bar_count = 0u;
            __threadfence();
            g_bar_gen = gen + 1u;
        } else {
            while (g_bar_gen == gen) { __nanosleep(64); }
            __threadfence();
        }
    }
    __syncthreads();
}

// ---------------- SGEMM: C[M,N] = A[M,K] * B[N,K]^T + bias[N] --------------
// 128x128 tile, K-step 8, 256 threads, 8x8 micro-tile (split 4+4 for
// conflict-free smem fragment loads).
__global__ void __launch_bounds__(256, 2)
sgemm_nt(const float* __restrict__ A, const float* __restrict__ Bm,
         const float* __restrict__ bias, float* __restrict__ C,
         int M, int N, int K)
{
    __shared__ float As[8][128];
    __shared__ float Bs[8][128];
    const int tid = threadIdx.x;
    const int m0 = blockIdx.y * 128;
    const int n0 = blockIdx.x * 128;
    const int tx = tid & 15;          // 0..15
    const int ty = tid >> 4;          // 0..15
    const int lrow = tid >> 1;        // 0..127
    const int lk4  = (tid & 1) * 4;   // 0 or 4

    const float* Ag = A + (size_t)(m0 + lrow) * K + lk4;
    const float* Bg = Bm + (size_t)(n0 + lrow) * K + lk4;

    float acc[8][8];
#pragma unroll
    for (int i = 0; i < 8; i++)
#pragma unroll
        for (int j = 0; j < 8; j++) acc[i][j] = 0.f;

    for (int k0 = 0; k0 < K; k0 += 8) {
        float4 av = *(const float4*)(Ag + k0);
        float4 bv = *(const float4*)(Bg + k0);
        __syncthreads();
        As[lk4 + 0][lrow] = av.x; As[lk4 + 1][lrow] = av.y;
        As[lk4 + 2][lrow] = av.z; As[lk4 + 3][lrow] = av.w;
        Bs[lk4 + 0][lrow] = bv.x; Bs[lk4 + 1][lrow] = bv.y;
        Bs[lk4 + 2][lrow] = bv.z; Bs[lk4 + 3][lrow] = bv.w;
        __syncthreads();
#pragma unroll
        for (int kk = 0; kk < 8; kk++) {
            float a[8], b[8];
            *(float4*)(a)     = *(const float4*)&As[kk][ty * 4];
            *(float4*)(a + 4) = *(const float4*)&As[kk][64 + ty * 4];
            *(float4*)(b)     = *(const float4*)&Bs[kk][tx * 4];
            *(float4*)(b + 4) = *(const float4*)&Bs[kk][64 + tx * 4];
#pragma unroll
            for (int i = 0; i < 8; i++)
#pragma unroll
                for (int j = 0; j < 8; j++)
                    acc[i][j] += a[i] * b[j];
        }
    }

    float bj[8];
#pragma unroll
    for (int jh = 0; jh < 2; jh++)
#pragma unroll
        for (int j = 0; j < 4; j++)
            bj[jh * 4 + j] = bias[n0 + jh * 64 + tx * 4 + j];

#pragma unroll
    for (int ih = 0; ih < 2; ih++) {
#pragma unroll
        for (int i = 0; i < 4; i++) {
            int row = m0 + ih * 64 + ty * 4 + i;
            float* cp = C + (size_t)row * N + n0;
            float4 v0, v1;
            v0.x = acc[ih * 4 + i][0] + bj[0];
            v0.y = acc[ih * 4 + i][1] + bj[1];
            v0.z = acc[ih * 4 + i][2] + bj[2];
            v0.w = acc[ih * 4 + i][3] + bj[3];
            v1.x = acc[ih * 4 + i][4] + bj[4];
            v1.y = acc[ih * 4 + i][5] + bj[5];
            v1.z = acc[ih * 4 + i][6] + bj[6];
            v1.w = acc[ih * 4 + i][7] + bj[7];
            *(float4*)(cp + tx * 4)      = v0;
            *(float4*)(cp + 64 + tx * 4) = v1;
        }
    }
}

// ---------------- persistent bidirectional LSTM -----------------------------
// 128 CTAs: dir = blockIdx.x/64, chunk = blockIdx.x%64 (8 h-dims each).
// W slice (32 rows x 512) cached in smem for the full scan. One grid barrier
// per timestep. smem rows padded to 516 floats -> conflict-free LDS.128 with
// the b = bb*8+bg / r = rr*4+rg lane mappings.
#define WPAD 516
#define LSTM_SMEM_FLOATS (32*WPAD + 32*WPAD + 8*32*33 + 32*33 + 32*8)
#define LSTM_SMEM_BYTES (LSTM_SMEM_FLOATS * 4)

__global__ void __launch_bounds__(256, 1)
lstm_kernel(const float* __restrict__ W_hh_f, const float* __restrict__ W_hh_b)
{
    extern __shared__ float sm[];
    float* Wsh  = sm;                       // [32][516]
    float* hsh  = Wsh + 32 * WPAD;          // [32][516]
    float* psum = hsh + 32 * WPAD;          // [8][32][33]
    float* gpre = psum + 8 * 32 * 33;       // [32][33]
    float* csh  = gpre + 32 * 33;           // [32][8]

    const int tid   = threadIdx.x;
    const int dir   = blockIdx.x >> 6;
    const int chunk = blockIdx.x & 63;
    const int j0    = chunk * 8;
    const float* xg  = dir ? g_xgb : g_xgf;
    const float* Whh = dir ? W_hh_b : W_hh_f;
    float* hs        = dir ? g_hb : g_hf;

    // load W slice: rows r=0..31 -> global row (r>>3)*512 + j0 + (r&7)
    for (int v = tid; v < 32 * 128; v += 256) {
        int r = v >> 7;
        int c4 = v & 127;
        int grow = ((r >> 3) << 9) + j0 + (r & 7);
        float4 w = *(const float4*)(Whh + (size_t)grow * Hn + c4 * 4);
        float* dst = Wsh + r * WPAD + c4 * 4;
        dst[0] = w.x; dst[1] = w.y; dst[2] = w.z; dst[3] = w.w;
    }
    {
        int b = tid >> 3, jj = tid & 7;
        csh[b * 8 + jj] = 0.f;
        g_hping[dir][0][b * Hn + j0 + jj] = 0.f;
    }
    grid_barrier(128);

    const int ks = tid >> 5;          // 0..7  (== warp id)
    const int bg = (tid >> 2) & 7;    // 0..7
    const int rg = tid & 3;           // 0..3

    for (int t = 0; t < Tn; t++) {
        const int p = t & 1;
        const int tact = dir ? (Tn - 1 - t) : t;

        // stage h into smem (padded)
        const float* hg = g_hping[dir][p];
        for (int v = tid; v < 32 * 128; v += 256) {
            int b = v >> 7, c4 = v & 127;
            float4 hv = *(const float4*)(hg + b * Hn + c4 * 4);
            float* dst = hsh + b * WPAD + c4 * 4;
            dst[0] = hv.x; dst[1] = hv.y; dst[2] = hv.z; dst[3] = hv.w;
        }
        __syncthreads();

        float acc[8][4];
#pragma unroll
        for (int i = 0; i < 8; i++)
#pragma unroll
            for (int j = 0; j < 4; j++) acc[i][j] = 0.f;

        const int kbase = ks * 64;
#pragma unroll 4
        for (int kv = 0; kv < 16; kv++) {
            int k = kbase + kv * 4;
            float4 hv[4];
#pragma unroll
            for (int bb = 0; bb < 4; bb++)
                hv[bb] = *(const float4*)(hsh + (bb * 8 + bg) * WPAD + k);
#pragma unroll
            for (int rr = 0; rr < 8; rr++) {
                float4 wv = *(const float4*)(Wsh + (rr * 4 + rg) * WPAD + k);
#pragma unroll
                for (int bb = 0; bb < 4; bb++) {
                    acc[rr][bb] += wv.x * hv[bb].x + wv.y * hv[bb].y
                                 + wv.z * hv[bb].z + wv.w * hv[bb].w;
                }
            }
        }
        // partials -> smem
#pragma unroll
        for (int rr = 0; rr < 8; rr++) {
            int r = rr * 4 + rg;
#pragma unroll
            for (int bb = 0; bb < 4; bb++)
                psum[(ks * 32 + r) * 33 + (bb * 8 + bg)] = acc[rr][bb];
        }
        __syncthreads();
        // reduce over k-slices
#pragma unroll
        for (int u = 0; u < 4; u++) {
            int idx = tid + u * 256;          // 0..1023
            int r = idx >> 5, b = idx & 31;
            float s = 0.f;
#pragma unroll
            for (int kk = 0; kk < 8; kk++) s += psum[(kk * 32 + r) * 33 + b];
            gpre[r * 33 + b] = s;
        }
        __syncthreads();
        // gate update: thread = (b, jj)
        {
            int b = tid >> 3, jj = tid & 7;
            size_t xbase = ((size_t)tact * Bn + b) * FOURH + j0 + jj;
            float gi = gpre[(jj) * 33 + b]      + xg[xbase];
            float gf = gpre[(8 + jj) * 33 + b]  + xg[xbase + 512];
            float gg = gpre[(16 + jj) * 33 + b] + xg[xbase + 1024];
            float go = gpre[(24 + jj) * 33 + b] + xg[xbase + 1536];
            float iv = 1.f / (1.f + expf(-gi));
            float fv = 1.f / (1.f + expf(-gf));
            float gv = tanhf(gg);
            float ov = 1.f / (1.f + expf(-go));
            float c = fv * csh[b * 8 + jj] + iv * gv;
            csh[b * 8 + jj] = c;
            float h = ov * tanhf(c);
            g_hping[dir][p ^ 1][b * Hn + j0 + jj] = h;
            hs[((size_t)tact * Bn + b) * Hn + j0 + jj] = h;
        }
        grid_barrier(128);
    }
}

// ---------------- feats: warp per (t,b) -------------------------------------
__global__ void __launch_bounds__(128)
feats_kernel(const float* __restrict__ W_lin, const float* __restrict__ b_lin)
{
    int warp = threadIdx.x >> 5, lane = threadIdx.x & 31;
    int idx = blockIdx.x * 4 + warp;        // t*32+b
    int t = idx >> 5, b = idx & 31;
    const float* hfp = g_hf + (size_t)idx * Hn;
    const float* hbp = g_hb + (size_t)idx * Hn;

    float hreg[16], hbreg[16];
#pragma unroll
    for (int i = 0; i < 16; i++) {
        hreg[i]  = hfp[lane + 32 * i];
        hbreg[i] = hbp[lane + 32 * i];
    }
    for (int k = 0; k < Kc; k++) {
        const float* wl = W_lin + k * (2 * Hn);
        float s = 0.f;
#pragma unroll
        for (int i = 0; i < 16; i++) {
            s += hreg[i]  * wl[lane + 32 * i];
            s += hbreg[i] * wl[512 + lane + 32 * i];
        }
#pragma unroll
        for (int o = 16; o; o >>= 1) s += __shfl_xor_sync(0xffffffffu, s, o);
        if (lane == 0)
            g_feats[((size_t)b * Tn + t) * Kc + k] = s + b_lin[k];
    }
}

// ---------------- CRF: warp per batch ---------------------------------------
__global__ void __launch_bounds__(32)
crf_kernel(const int* __restrict__ tags, const float* __restrict__ trans,
           float* __restrict__ out)
{
    int b = blockIdx.x, lane = threadIdx.x;
    float tr[Kc];
#pragma unroll
    for (int j = 0; j < Kc; j++)
        tr[j] = (lane < Kc) ? trans[lane * Kc + j] : 0.f;

    float alpha = (lane == START_TAG) ? 0.f : -10000.f;
    const float* fb = g_feats + (size_t)b * Tn * Kc;

    for (int t = 0; t < Tn; t++) {
        float m = -3.4e38f, s = 0.f;
#pragma unroll
        for (int j = 0; j < Kc; j++) {
            float aj = __shfl_sync(0xffffffffu, alpha, j);
            float v = aj + tr[j];
            if (v > m) { s = s * expf(m - v) + 1.f; m = v; }
            else       { s += expf(v - m); }
        }
        float e = (lane < Kc) ? fb[t * Kc + lane] : 0.f;
        alpha = m + logf(s) + e;
        if (lane >= Kc) alpha = -3.4e38f;
    }

    // log_Z
    float v = (lane < Kc) ? alpha + trans[STOP_TAG * Kc + lane] : -3.4e38f;
    float m = v;
#pragma unroll
    for (int o = 16; o; o >>= 1) m = fmaxf(m, __shfl_xor_sync(0xffffffffu, m, o));
    float se = (lane < Kc) ? expf(v - m) : 0.f;
#pragma unroll
    for (int o = 16; o; o >>= 1) se += __shfl_xor_sync(0xffffffffu, se, o);
    float logZ = m + logf(se);

    // gold path score
    const int* tg = tags + b * Tn;
    float ts = 0.f, es = 0.f;
    for (int t = lane; t < Tn; t += 32) {
        int nxt = tg[t];
        int prev = (t == 0) ? START_TAG : tg[t - 1];
        ts += trans[nxt * Kc + prev];
        es += fb[t * Kc + nxt];
    }
    if (lane == 0) ts += trans[STOP_TAG * Kc + tg[Tn - 1]];
#pragma unroll
    for (int o = 16; o; o >>= 1) {
        ts += __shfl_xor_sync(0xffffffffu, ts, o);
        es += __shfl_xor_sync(0xffffffffu, es, o);
    }
    if (lane == 0) out[b] = logZ - (ts + es);
}

// ---------------- launch -----------------------------------------------------
extern "C" void kernel_launch(void* const* d_in, const int* in_sizes, int n_in,
                              void* d_out, int out_size)
{
    const float* x      = (const float*)d_in[0];
    const int*   tags   = (const int*)d_in[1];
    const float* W_e2n  = (const float*)d_in[2];
    const float* b_e2n  = (const float*)d_in[3];
    const float* W_ih_f = (const float*)d_in[4];
    const float* W_hh_f = (const float*)d_in[5];
    const float* b_f    = (const float*)d_in[6];
    const float* W_ih_b = (const float*)d_in[7];
    const float* W_hh_b = (const float*)d_in[8];
    const float* b_b    = (const float*)d_in[9];
    const float* W_lin  = (const float*)d_in[10];
    const float* b_lin  = (const float*)d_in[11];
    const float* trans  = (const float*)d_in[12];
    float* out = (float*)d_out;

    float *xn, *xgf, *xgb;
    cudaGetSymbolAddress((void**)&xn,  g_xn);
    cudaGetSymbolAddress((void**)&xgf, g_xgf);
    cudaGetSymbolAddress((void**)&xgb, g_xgb);

    cudaFuncSetAttribute(lstm_kernel,
                         cudaFuncAttributeMaxDynamicSharedMemorySize,
                         LSTM_SMEM_BYTES);

    // 1) xn = x @ W_e2n^T + b_e2n   (4096x4096x4096)
    {
        dim3 grid(En / 128, TB / 128);
        sgemm_nt<<<grid, 256>>>(x, W_e2n, b_e2n, xn, TB, En, En);
    }
    // 2) xg_f / xg_b = xn @ W_ih^T + b   (4096x2048x4096 each)
    {
        dim3 grid(FOURH / 128, TB / 128);
        sgemm_nt<<<grid, 256>>>(xn, W_ih_f, b_f, xgf, TB, FOURH, En);
        sgemm_nt<<<grid, 256>>>(xn, W_ih_b, b_b, xgb, TB, FOURH, En);
    }
    // 3) bidirectional LSTM scan (persistent, grid-barriered)
    lstm_kernel<<<128, 256, LSTM_SMEM_BYTES>>>(W_hh_f, W_hh_b);

    // 4) feats = [hf|hb] @ W_lin^T + b_lin  -> [B,T,K]
    feats_kernel<<<TB / 4, 128>>>(W_lin, b_lin);

    // 5) CRF forward + gold score -> NLL per batch
    crf_kernel<<<Bn, 32>>>(tags, trans, out);
}

// round 3
// speedup vs baseline: 3.4036x; 3.4036x over previous
#include <cuda_runtime.h>
#include <cuda_bf16.h>
#include <math.h>
#include <stdint.h>

// ---------------- problem constants ----------------
#define Tn 128
#define Bn 32
#define En 4096
#define Hn 512
#define FOURH 2048
#define TB 4096          // T*B
#define Kc 20
#define START_TAG 18
#define STOP_TAG 19

// ---------------- scratch (device globals; allocation-free) ----------------
__device__ __align__(256) __nv_bfloat16 g_xbf[(size_t)TB * En];
__device__ __align__(256) __nv_bfloat16 g_we2n_bf[(size_t)En * En];
__device__ __align__(256) __nv_bfloat16 g_xnbf[(size_t)TB * En];
__device__ __align__(256) __nv_bfloat16 g_wihf_bf[(size_t)FOURH * En];
__device__ __align__(256) __nv_bfloat16 g_wihb_bf[(size_t)FOURH * En];
__device__ float g_xgf[(size_t)TB * FOURH];
__device__ float g_xgb[(size_t)TB * FOURH];
__device__ float g_hf[(size_t)TB * Hn];
__device__ float g_hb[(size_t)TB * Hn];
__device__ float g_hping[2][2][Bn * Hn];
__device__ float g_feats[(size_t)Bn * Tn * Kc];

__device__ unsigned g_bar_count = 0;
__device__ volatile unsigned g_bar_gen = 0;

// ================= helpers ===================================================
__device__ __forceinline__ uint32_t smem_to_u32(const void* p) {
    uint32_t a;
    asm("{ .reg .u64 t; cvta.to.shared.u64 t, %1; cvt.u32.u64 %0, t; }"
        : "=r"(a) : "l"(p));
    return a;
}
#define SW128(o) ((o) ^ (((o) >> 3) & 0x70))

__device__ __forceinline__ void cp_async16(uint32_t dst, const void* src) {
    asm volatile("cp.async.cg.shared.global [%0], [%1], 16;" :: "r"(dst), "l"(src));
}
#define CP_COMMIT() asm volatile("cp.async.commit_group;" ::: "memory")
#define CP_WAIT_1() asm volatile("cp.async.wait_group 1;" ::: "memory")

__device__ __forceinline__ void ldsm_x4(uint32_t addr, uint32_t& r0, uint32_t& r1,
                                        uint32_t& r2, uint32_t& r3) {
    asm volatile("ldmatrix.sync.aligned.m8n8.x4.shared.b16 {%0,%1,%2,%3}, [%4];"
                 : "=r"(r0), "=r"(r1), "=r"(r2), "=r"(r3) : "r"(addr));
}

__device__ __forceinline__ void mma16816(float* d, const uint32_t* a, const uint32_t* b) {
    asm volatile(
        "mma.sync.aligned.m16n8k16.row.col.f32.bf16.bf16.f32 "
        "{%0,%1,%2,%3}, {%4,%5,%6,%7}, {%8,%9}, {%0,%1,%2,%3};"
        : "+f"(d[0]), "+f"(d[1]), "+f"(d[2]), "+f"(d[3])
        : "r"(a[0]), "r"(a[1]), "r"(a[2]), "r"(a[3]), "r"(b[0]), "r"(b[1]));
}

// ================= HMMA GEMM: C[M,N] = A[M,K]bf16 @ B[N,K]bf16^T + bias ======
// CTA tile 128x128, K-step 64 (128B rows, SW128), 3-stage cp.async.
// 8 warps: warp_m = wid&3 (m: 32), warp_n = wid>>2 (n: 64). Warp tile 32x64.
#define GSTAGE_BYTES 32768                 // A 16KB + B 16KB
#define GEMM_SMEM_BYTES (3 * GSTAGE_BYTES)

template <bool OUT_BF16>
__global__ void __launch_bounds__(256)
gemm_hmma(const __nv_bfloat16* __restrict__ Aq, const __nv_bfloat16* __restrict__ Bq,
          const float* __restrict__ bias, void* __restrict__ Cout,
          int M, int N, int K)
{
    extern __shared__ __align__(1024) char smem[];
    const uint32_t sb = smem_to_u32(smem);

    const int tid = threadIdx.x;
    const int wid = tid >> 5;
    const int lane = tid & 31;
    const int warp_m = wid & 3;
    const int warp_n = wid >> 2;
    const int m0 = blockIdx.y * 128;
    const int n0 = blockIdx.x * 128;
    const int NKT = K / 64;

    // cp.async source/dest mapping: idx -> row idx>>3, 16B chunk idx&7
    const int ldr = tid >> 3;
    const int ldc = tid & 7;

#define G_LOAD(kt) do { \
        if ((kt) < NKT) { \
            const uint32_t st = sb + ((kt) % 3) * GSTAGE_BYTES; \
            int _k0 = (kt) * 64; \
            _Pragma("unroll") \
            for (int _p = 0; _p < 4; _p++) { \
                int _r = ldr + _p * 32; \
                cp_async16(st + SW128(_r * 128 + ldc * 16), \
                           Aq + (size_t)(m0 + _r) * K + _k0 + ldc * 8); \
            } \
            _Pragma("unroll") \
            for (int _p = 0; _p < 4; _p++) { \
                int _r = ldr + _p * 32; \
                cp_async16(st + 16384 + SW128(_r * 128 + ldc * 16), \
                           Bq + (size_t)(n0 + _r) * K + _k0 + ldc * 8); \
            } \
        } \
        CP_COMMIT(); \
    } while (0)

    float d[2][8][4];
#pragma unroll
    for (int mi = 0; mi < 2; mi++)
#pragma unroll
        for (int ni = 0; ni < 8; ni++)
#pragma unroll
            for (int q = 0; q < 4; q++) d[mi][ni][q] = 0.f;

    // per-lane ldmatrix base offsets (bytes within tile)
    const int aRow = warp_m * 32 + (lane & 15);
    const int aColB = (lane >> 4) * 16;
    const int bRow = warp_n * 64 + (lane & 7) + (lane >> 4) * 8;
    const int bColB = ((lane >> 3) & 1) * 16;

    G_LOAD(0);
    G_LOAD(1);

    for (int i = 0; i < NKT; i++) {
        CP_WAIT_1();
        __syncthreads();
        G_LOAD(i + 2);

        const uint32_t stA = sb + (i % 3) * GSTAGE_BYTES;
        const uint32_t stB = stA + 16384;
#pragma unroll
        for (int ks = 0; ks < 4; ks++) {
            const int kb = ks * 32;   // byte offset of k16 step
            uint32_t a[2][4];
#pragma unroll
            for (int mi = 0; mi < 2; mi++)
                ldsm_x4(stA + SW128((aRow + mi * 16) * 128 + kb + aColB),
                        a[mi][0], a[mi][1], a[mi][2], a[mi][3]);
            uint32_t b[8][2];
#pragma unroll
            for (int np = 0; np < 4; np++) {
                uint32_t r0, r1, r2, r3;
                ldsm_x4(stB + SW128((bRow + np * 16) * 128 + kb + bColB),
                        r0, r1, r2, r3);
                b[np * 2][0] = r0; b[np * 2][1] = r1;
                b[np * 2 + 1][0] = r2; b[np * 2 + 1][1] = r3;
            }
#pragma unroll
            for (int mi = 0; mi < 2; mi++)
#pragma unroll
                for (int ni = 0; ni < 8; ni++)
                    mma16816(d[mi][ni], a[mi], b[ni]);
        }
    }

    // epilogue: direct global stores with fused bias
    const int qrow = lane >> 2;
    const int qcol = (lane & 3) * 2;
#pragma unroll
    for (int mi = 0; mi < 2; mi++) {
#pragma unroll
        for (int ni = 0; ni < 8; ni++) {
            const int col = n0 + warp_n * 64 + ni * 8 + qcol;
            const int row = m0 + warp_m * 32 + mi * 16 + qrow;
            const float b0 = bias[col], b1 = bias[col + 1];
            float v00 = d[mi][ni][0] + b0, v01 = d[mi][ni][1] + b1;
            float v10 = d[mi][ni][2] + b0, v11 = d[mi][ni][3] + b1;
            if (OUT_BF16) {
                __nv_bfloat16* C = (__nv_bfloat16*)Cout;
                __nv_bfloat162 p0 = __floats2bfloat162_rn(v00, v01);
                __nv_bfloat162 p1 = __floats2bfloat162_rn(v10, v11);
                *(__nv_bfloat162*)(C + (size_t)row * N + col) = p0;
                *(__nv_bfloat162*)(C + (size_t)(row + 8) * N + col) = p1;
            } else {
                float* C = (float*)Cout;
                *(float2*)(C + (size_t)row * N + col) = make_float2(v00, v01);
                *(float2*)(C + (size_t)(row + 8) * N + col) = make_float2(v10, v11);
            }
        }
    }
}

// ================= fp32 -> bf16 conversion ===================================
__global__ void __launch_bounds__(256)
cvt_f32_bf16(const float* __restrict__ in, __nv_bfloat16* __restrict__ out, int n)
{
    int base = (blockIdx.x * 256 + threadIdx.x) * 8;
    if (base >= n) return;
    float4 a = *(const float4*)(in + base);
    float4 b = *(const float4*)(in + base + 4);
    union { __nv_bfloat16 h[8]; uint4 v; } u;
    u.h[0] = __float2bfloat16(a.x); u.h[1] = __float2bfloat16(a.y);
    u.h[2] = __float2bfloat16(a.z); u.h[3] = __float2bfloat16(a.w);
    u.h[4] = __float2bfloat16(b.x); u.h[5] = __float2bfloat16(b.y);
    u.h[6] = __float2bfloat16(b.z); u.h[7] = __float2bfloat16(b.w);
    *(uint4*)(out + base) = u.v;
}

// ---------------- grid barrier ----------------------------------------------
__device__ __forceinline__ void grid_barrier(unsigned nb) {
    __syncthreads();
    if (threadIdx.x == 0) {
        unsigned gen = g_bar_gen;
        __threadfence();
        if (atomicAdd(&g_bar_count, 1u) == nb - 1u) {
            g_bar_count = 0u;
            __threadfence();
            g_bar_gen = gen + 1u;
        } else {
            while (g_bar_gen == gen) { __nanosleep(64); }
            __threadfence();
        }
    }
    __syncthreads();
}

// ---------------- persistent bidirectional LSTM -----------------------------
#define WPAD 516
#define LSTM_SMEM_FLOATS (32*WPAD + 32*WPAD + 8*32*33 + 32*33 + 32*8)
#define LSTM_SMEM_BYTES (LSTM_SMEM_FLOATS * 4)

__global__ void __launch_bounds__(256, 1)
lstm_kernel(const float* __restrict__ W_hh_f, const float* __restrict__ W_hh_b)
{
    extern __shared__ float sm[];
    float* Wsh  = sm;
    float* hsh  = Wsh + 32 * WPAD;
    float* psum = hsh + 32 * WPAD;
    float* gpre = psum + 8 * 32 * 33;
    float* csh  = gpre + 32 * 33;

    const int tid   = threadIdx.x;
    const int dir   = blockIdx.x >> 6;
    const int chunk = blockIdx.x & 63;
    const int j0    = chunk * 8;
    const float* xg  = dir ? g_xgb : g_xgf;
    const float* Whh = dir ? W_hh_b : W_hh_f;
    float* hs        = dir ? g_hb : g_hf;

    for (int v = tid; v < 32 * 128; v += 256) {
        int r = v >> 7;
        int c4 = v & 127;
        int grow = ((r >> 3) << 9) + j0 + (r & 7);
        float4 w = *(const float4*)(Whh + (size_t)grow * Hn + c4 * 4);
        float* dst = Wsh + r * WPAD + c4 * 4;
        dst[0] = w.x; dst[1] = w.y; dst[2] = w.z; dst[3] = w.w;
    }
    {
        int b = tid >> 3, jj = tid & 7;
        csh[b * 8 + jj] = 0.f;
        g_hping[dir][0][b * Hn + j0 + jj] = 0.f;
    }
    grid_barrier(128);

    const int ks = tid >> 5;
    const int bg = (tid >> 2) & 7;
    const int rg = tid & 3;

    for (int t = 0; t < Tn; t++) {
        const int p = t & 1;
        const int tact = dir ? (Tn - 1 - t) : t;

        const float* hg = g_hping[dir][p];
        for (int v = tid; v < 32 * 128; v += 256) {
            int b = v >> 7, c4 = v & 127;
            float4 hv = *(const float4*)(hg + b * Hn + c4 * 4);
            float* dst = hsh + b * WPAD + c4 * 4;
            dst[0] = hv.x; dst[1] = hv.y; dst[2] = hv.z; dst[3] = hv.w;
        }
        __syncthreads();

        float acc[8][4];
#pragma unroll
        for (int i = 0; i < 8; i++)
#pragma unroll
            for (int j = 0; j < 4; j++) acc[i][j] = 0.f;

        const int kbase = ks * 64;
#pragma unroll 4
        for (int kv = 0; kv < 16; kv++) {
            int k = kbase + kv * 4;
            float4 hv[4];
#pragma unroll
            for (int bb = 0; bb < 4; bb++)
                hv[bb] = *(const float4*)(hsh + (bb * 8 + bg) * WPAD + k);
#pragma unroll
            for (int rr = 0; rr < 8; rr++) {
                float4 wv = *(const float4*)(Wsh + (rr * 4 + rg) * WPAD + k);
#pragma unroll
                for (int bb = 0; bb < 4; bb++) {
                    acc[rr][bb] += wv.x * hv[bb].x + wv.y * hv[bb].y
                                 + wv.z * hv[bb].z + wv.w * hv[bb].w;
                }
            }
        }
#pragma unroll
        for (int rr = 0; rr < 8; rr++) {
            int r = rr * 4 + rg;
#pragma unroll
            for (int bb = 0; bb < 4; bb++)
                psum[(ks * 32 + r) * 33 + (bb * 8 + bg)] = acc[rr][bb];
        }
        __syncthreads();
#pragma unroll
        for (int u = 0; u < 4; u++) {
            int idx = tid + u * 256;
            int r = idx >> 5, b = idx & 31;
            float s = 0.f;
#pragma unroll
            for (int kk = 0; kk < 8; kk++) s += psum[(kk * 32 + r) * 33 + b];
            gpre[r * 33 + b] = s;
        }
        __syncthreads();
        {
            int b = tid >> 3, jj = tid & 7;
            size_t xbase = ((size_t)tact * Bn + b) * FOURH + j0 + jj;
            float gi = gpre[(jj) * 33 + b]      + xg[xbase];
            float gf = gpre[(8 + jj) * 33 + b]  + xg[xbase + 512];
            float gg = gpre[(16 + jj) * 33 + b] + xg[xbase + 1024];
            float go = gpre[(24 + jj) * 33 + b] + xg[xbase + 1536];
            float iv = 1.f / (1.f + expf(-gi));
            float fv = 1.f / (1.f + expf(-gf));
            float gv = tanhf(gg);
            float ov = 1.f / (1.f + expf(-go));
            float c = fv * csh[b * 8 + jj] + iv * gv;
            csh[b * 8 + jj] = c;
            float h = ov * tanhf(c);
            g_hping[dir][p ^ 1][b * Hn + j0 + jj] = h;
            hs[((size_t)tact * Bn + b) * Hn + j0 + jj] = h;
        }
        grid_barrier(128);
    }
}

// ---------------- feats: warp per (t,b) -------------------------------------
__global__ void __launch_bounds__(128)
feats_kernel(const float* __restrict__ W_lin, const float* __restrict__ b_lin)
{
    int warp = threadIdx.x >> 5, lane = threadIdx.x & 31;
    int idx = blockIdx.x * 4 + warp;
    int t = idx >> 5, b = idx & 31;
    const float* hfp = g_hf + (size_t)idx * Hn;
    const float* hbp = g_hb + (size_t)idx * Hn;

    float hreg[16], hbreg[16];
#pragma unroll
    for (int i = 0; i < 16; i++) {
        hreg[i]  = hfp[lane + 32 * i];
        hbreg[i] = hbp[lane + 32 * i];
    }
    for (int k = 0; k < Kc; k++) {
        const float* wl = W_lin + k * (2 * Hn);
        float s = 0.f;
#pragma unroll
        for (int i = 0; i < 16; i++) {
            s += hreg[i]  * wl[lane + 32 * i];
            s += hbreg[i] * wl[512 + lane + 32 * i];
        }
#pragma unroll
        for (int o = 16; o; o >>= 1) s += __shfl_xor_sync(0xffffffffu, s, o);
        if (lane == 0)
            g_feats[((size_t)b * Tn + t) * Kc + k] = s + b_lin[k];
    }
}

// ---------------- CRF: warp per batch ---------------------------------------
__global__ void __launch_bounds__(32)
crf_kernel(const int* __restrict__ tags, const float* __restrict__ trans,
           float* __restrict__ out)
{
    int b = blockIdx.x, lane = threadIdx.x;
    float tr[Kc];
#pragma unroll
    for (int j = 0; j < Kc; j++)
        tr[j] = (lane < Kc) ? trans[lane * Kc + j] : 0.f;

    float alpha = (lane == START_TAG) ? 0.f : -10000.f;
    const float* fb = g_feats + (size_t)b * Tn * Kc;

    for (int t = 0; t < Tn; t++) {
        float m = -3.4e38f, s = 0.f;
#pragma unroll
        for (int j = 0; j < Kc; j++) {
            float aj = __shfl_sync(0xffffffffu, alpha, j);
            float v = aj + tr[j];
            if (v > m) { s = s * expf(m - v) + 1.f; m = v; }
            else       { s += expf(v - m); }
        }
        float e = (lane < Kc) ? fb[t * Kc + lane] : 0.f;
        alpha = m + logf(s) + e;
        if (lane >= Kc) alpha = -3.4e38f;
    }

    float v = (lane < Kc) ? alpha + trans[STOP_TAG * Kc + lane] : -3.4e38f;
    float m = v;
#pragma unroll
    for (int o = 16; o; o >>= 1) m = fmaxf(m, __shfl_xor_sync(0xffffffffu, m, o));
    float se = (lane < Kc) ? expf(v - m) : 0.f;
#pragma unroll
    for (int o = 16; o; o >>= 1) se += __shfl_xor_sync(0xffffffffu, se, o);
    float logZ = m + logf(se);

    const int* tg = tags + b * Tn;
    float ts = 0.f, es = 0.f;
    for (int t = lane; t < Tn; t += 32) {
        int nxt = tg[t];
        int prev = (t == 0) ? START_TAG : tg[t - 1];
        ts += trans[nxt * Kc + prev];
        es += fb[t * Kc + nxt];
    }
    if (lane == 0) ts += trans[STOP_TAG * Kc + tg[Tn - 1]];
#pragma unroll
    for (int o = 16; o; o >>= 1) {
        ts += __shfl_xor_sync(0xffffffffu, ts, o);
        es += __shfl_xor_sync(0xffffffffu, es, o);
    }
    if (lane == 0) out[b] = logZ - (ts + es);
}

// ---------------- launch -----------------------------------------------------
extern "C" void kernel_launch(void* const* d_in, const int* in_sizes, int n_in,
                              void* d_out, int out_size)
{
    const float* x      = (const float*)d_in[0];
    const int*   tags   = (const int*)d_in[1];
    const float* W_e2n  = (const float*)d_in[2];
    const float* b_e2n  = (const float*)d_in[3];
    const float* W_ih_f = (const float*)d_in[4];
    const float* W_hh_f = (const float*)d_in[5];
    const float* b_f    = (const float*)d_in[6];
    const float* W_ih_b = (const float*)d_in[7];
    const float* W_hh_b = (const float*)d_in[8];
    const float* b_b    = (const float*)d_in[9];
    const float* W_lin  = (const float*)d_in[10];
    const float* b_lin  = (const float*)d_in[11];
    const float* trans  = (const float*)d_in[12];
    float* out = (float*)d_out;

    __nv_bfloat16 *xbf, *we2nbf, *xnbf, *wihfbf, *wihbbf;
    float *xgf, *xgb;
    cudaGetSymbolAddress((void**)&xbf,    g_xbf);
    cudaGetSymbolAddress((void**)&we2nbf, g_we2n_bf);
    cudaGetSymbolAddress((void**)&xnbf,   g_xnbf);
    cudaGetSymbolAddress((void**)&wihfbf, g_wihf_bf);
    cudaGetSymbolAddress((void**)&wihbbf, g_wihb_bf);
    cudaGetSymbolAddress((void**)&xgf,    g_xgf);
    cudaGetSymbolAddress((void**)&xgb,    g_xgb);

    cudaFuncSetAttribute(lstm_kernel,
                         cudaFuncAttributeMaxDynamicSharedMemorySize,
                         LSTM_SMEM_BYTES);
    cudaFuncSetAttribute(gemm_hmma<true>,
                         cudaFuncAttributeMaxDynamicSharedMemorySize,
                         GEMM_SMEM_BYTES);
    cudaFuncSetAttribute(gemm_hmma<false>,
                         cudaFuncAttributeMaxDynamicSharedMemorySize,
                         GEMM_SMEM_BYTES);

    // 0) fp32 -> bf16 conversions
    cvt_f32_bf16<<<(TB * En) / (256 * 8), 256>>>(x, xbf, TB * En);
    cvt_f32_bf16<<<(En * En) / (256 * 8), 256>>>(W_e2n, we2nbf, En * En);
    cvt_f32_bf16<<<(FOURH * En) / (256 * 8), 256>>>(W_ih_f, wihfbf, FOURH * En);
    cvt_f32_bf16<<<(FOURH * En) / (256 * 8), 256>>>(W_ih_b, wihbbf, FOURH * En);

    // 1) xn = x @ W_e2n^T + b_e2n  (bf16 out)
    {
        dim3 grid(En / 128, TB / 128);
        gemm_hmma<true><<<grid, 256, GEMM_SMEM_BYTES>>>(xbf, we2nbf, b_e2n, xnbf, TB, En, En);
    }
    // 2) xg_f / xg_b = xn @ W_ih^T + b  (fp32 out)
    {
        dim3 grid(FOURH / 128, TB / 128);
        gemm_hmma<false><<<grid, 256, GEMM_SMEM_BYTES>>>(xnbf, wihfbf, b_f, xgf, TB, FOURH, En);
        gemm_hmma<false><<<grid, 256, GEMM_SMEM_BYTES>>>(xnbf, wihbbf, b_b, xgb, TB, FOURH, En);
    }
    // 3) bidirectional LSTM scan
    lstm_kernel<<<128, 256, LSTM_SMEM_BYTES>>>(W_hh_f, W_hh_b);

    // 4) feats
    feats_kernel<<<TB / 4, 128>>>(W_lin, b_lin);

    // 5) CRF
    crf_kernel<<<Bn, 32>>>(tags, trans, out);
}

// round 4
// speedup vs baseline: 4.5360x; 1.3327x over previous
#include <cuda_runtime.h>
#include <cuda_bf16.h>
#include <math.h>
#include <stdint.h>

// ---------------- problem constants ----------------
#define Tn 128
#define Bn 32
#define En 4096
#define Hn 512
#define FOURH 2048
#define TB 4096          // T*B
#define Kc 20
#define START_TAG 18
#define STOP_TAG 19

// ---------------- scratch (device globals; allocation-free) ----------------
__device__ __align__(256) __nv_bfloat16 g_xbf[(size_t)TB * En];
__device__ __align__(256) __nv_bfloat16 g_we2n_bf[(size_t)En * En];
__device__ __align__(256) __nv_bfloat16 g_xnbf[(size_t)TB * En];
__device__ __align__(256) __nv_bfloat16 g_wihf_bf[(size_t)FOURH * En];
__device__ __align__(256) __nv_bfloat16 g_wihb_bf[(size_t)FOURH * En];
__device__ __align__(256) __nv_bfloat16 g_whhf_bf[(size_t)FOURH * Hn];
__device__ __align__(256) __nv_bfloat16 g_whhb_bf[(size_t)FOURH * Hn];
__device__ float g_xgf[(size_t)TB * FOURH];
__device__ float g_xgb[(size_t)TB * FOURH];
__device__ float g_hf[(size_t)TB * Hn];
__device__ float g_hb[(size_t)TB * Hn];
__device__ __align__(256) __nv_bfloat16 g_hping_bf[2][2][Bn * Hn];
__device__ float g_feats[(size_t)Bn * Tn * Kc];

__device__ unsigned g_bar_count = 0;
__device__ volatile unsigned g_bar_gen = 0;

// ================= helpers ===================================================
__device__ __forceinline__ uint32_t smem_to_u32(const void* p) {
    uint32_t a;
    asm("{ .reg .u64 t; cvta.to.shared.u64 t, %1; cvt.u32.u64 %0, t; }"
        : "=r"(a) : "l"(p));
    return a;
}
#define SW128(o) ((o) ^ (((o) >> 3) & 0x70))

__device__ __forceinline__ void cp_async16(uint32_t dst, const void* src) {
    asm volatile("cp.async.cg.shared.global [%0], [%1], 16;" :: "r"(dst), "l"(src));
}
#define CP_COMMIT() asm volatile("cp.async.commit_group;" ::: "memory")
#define CP_WAIT_1() asm volatile("cp.async.wait_group 1;" ::: "memory")
#define CP_WAIT_0() asm volatile("cp.async.wait_group 0;" ::: "memory")

__device__ __forceinline__ void ldsm_x4(uint32_t addr, uint32_t& r0, uint32_t& r1,
                                        uint32_t& r2, uint32_t& r3) {
    asm volatile("ldmatrix.sync.aligned.m8n8.x4.shared.b16 {%0,%1,%2,%3}, [%4];"
                 : "=r"(r0), "=r"(r1), "=r"(r2), "=r"(r3) : "r"(addr));
}

__device__ __forceinline__ void mma16816(float* d, const uint32_t* a, const uint32_t* b) {
    asm volatile(
        "mma.sync.aligned.m16n8k16.row.col.f32.bf16.bf16.f32 "
        "{%0,%1,%2,%3}, {%4,%5,%6,%7}, {%8,%9}, {%0,%1,%2,%3};"
        : "+f"(d[0]), "+f"(d[1]), "+f"(d[2]), "+f"(d[3])
        : "r"(a[0]), "r"(a[1]), "r"(a[2]), "r"(a[3]), "r"(b[0]), "r"(b[1]));
}

// ================= HMMA GEMM: C[M,N] = A[M,K]bf16 @ B[N,K]bf16^T + bias ======
#define GSTAGE_BYTES 32768
#define GEMM_SMEM_BYTES (3 * GSTAGE_BYTES)

template <bool OUT_BF16, bool DUAL>
__global__ void __launch_bounds__(256)
gemm_hmma(const __nv_bfloat16* __restrict__ Aq, const __nv_bfloat16* __restrict__ Bq0,
          const __nv_bfloat16* __restrict__ Bq1,
          const float* __restrict__ bias0, const float* __restrict__ bias1,
          void* __restrict__ Cout0, void* __restrict__ Cout1,
          int M, int N, int K, int nbx)
{
    extern __shared__ __align__(1024) char smem[];
    const uint32_t sb = smem_to_u32(smem);

    const int tid = threadIdx.x;
    const int wid = tid >> 5;
    const int lane = tid & 31;
    const int warp_m = wid & 3;
    const int warp_n = wid >> 2;
    int bx = blockIdx.x;
    const __nv_bfloat16* Bq = Bq0;
    const float* bias = bias0;
    void* Cout = Cout0;
    if (DUAL && bx >= nbx) {
        bx -= nbx; Bq = Bq1; bias = bias1; Cout = Cout1;
    }
    const int m0 = blockIdx.y * 128;
    const int n0 = bx * 128;
    const int NKT = K / 64;

    const int ldr = tid >> 3;
    const int ldc = tid & 7;

#define G_LOAD(kt) do { \
        if ((kt) < NKT) { \
            const uint32_t st = sb + ((kt) % 3) * GSTAGE_BYTES; \
            int _k0 = (kt) * 64; \
            _Pragma("unroll") \
            for (int _p = 0; _p < 4; _p++) { \
                int _r = ldr + _p * 32; \
                cp_async16(st + SW128(_r * 128 + ldc * 16), \
                           Aq + (size_t)(m0 + _r) * K + _k0 + ldc * 8); \
            } \
            _Pragma("unroll") \
            for (int _p = 0; _p < 4; _p++) { \
                int _r = ldr + _p * 32; \
                cp_async16(st + 16384 + SW128(_r * 128 + ldc * 16), \
                           Bq + (size_t)(n0 + _r) * K + _k0 + ldc * 8); \
            } \
        } \
        CP_COMMIT(); \
    } while (0)

    float d[2][8][4];
#pragma unroll
    for (int mi = 0; mi < 2; mi++)
#pragma unroll
        for (int ni = 0; ni < 8; ni++)
#pragma unroll
            for (int q = 0; q < 4; q++) d[mi][ni][q] = 0.f;

    const int aRow = warp_m * 32 + (lane & 15);
    const int aColB = (lane >> 4) * 16;
    const int bRow = warp_n * 64 + (lane & 7) + (lane >> 4) * 8;
    const int bColB = ((lane >> 3) & 1) * 16;

    G_LOAD(0);
    G_LOAD(1);

    for (int i = 0; i < NKT; i++) {
        CP_WAIT_1();
        __syncthreads();
        G_LOAD(i + 2);

        const uint32_t stA = sb + (i % 3) * GSTAGE_BYTES;
        const uint32_t stB = stA + 16384;
#pragma unroll
        for (int ks = 0; ks < 4; ks++) {
            const int kb = ks * 32;
            uint32_t a[2][4];
#pragma unroll
            for (int mi = 0; mi < 2; mi++)
                ldsm_x4(stA + SW128((aRow + mi * 16) * 128 + kb + aColB),
                        a[mi][0], a[mi][1], a[mi][2], a[mi][3]);
            uint32_t b[8][2];
#pragma unroll
            for (int np = 0; np < 4; np++) {
                uint32_t r0, r1, r2, r3;
                ldsm_x4(stB + SW128((bRow + np * 16) * 128 + kb + bColB),
                        r0, r1, r2, r3);
                b[np * 2][0] = r0; b[np * 2][1] = r1;
                b[np * 2 + 1][0] = r2; b[np * 2 + 1][1] = r3;
            }
#pragma unroll
            for (int mi = 0; mi < 2; mi++)
#pragma unroll
                for (int ni = 0; ni < 8; ni++)
                    mma16816(d[mi][ni], a[mi], b[ni]);
        }
    }

    const int qrow = lane >> 2;
    const int qcol = (lane & 3) * 2;
#pragma unroll
    for (int mi = 0; mi < 2; mi++) {
#pragma unroll
        for (int ni = 0; ni < 8; ni++) {
            const int col = n0 + warp_n * 64 + ni * 8 + qcol;
            const int row = m0 + warp_m * 32 + mi * 16 + qrow;
            const float b0 = bias[col], b1 = bias[col + 1];
            float v00 = d[mi][ni][0] + b0, v01 = d[mi][ni][1] + b1;
            float v10 = d[mi][ni][2] + b0, v11 = d[mi][ni][3] + b1;
            if (OUT_BF16) {
                __nv_bfloat16* C = (__nv_bfloat16*)Cout;
                __nv_bfloat162 p0 = __floats2bfloat162_rn(v00, v01);
                __nv_bfloat162 p1 = __floats2bfloat162_rn(v10, v11);
                *(__nv_bfloat162*)(C + (size_t)row * N + col) = p0;
                *(__nv_bfloat162*)(C + (size_t)(row + 8) * N + col) = p1;
            } else {
                float* C = (float*)Cout;
                *(float2*)(C + (size_t)row * N + col) = make_float2(v00, v01);
                *(float2*)(C + (size_t)(row + 8) * N + col) = make_float2(v10, v11);
            }
        }
    }
}

// ================= fp32 -> bf16 conversion ===================================
__global__ void __launch_bounds__(256)
cvt_f32_bf16(const float* __restrict__ in, __nv_bfloat16* __restrict__ out, int n)
{
    int base = (blockIdx.x * 256 + threadIdx.x) * 8;
    if (base >= n) return;
    float4 a = *(const float4*)(in + base);
    float4 b = *(const float4*)(in + base + 4);
    union { __nv_bfloat16 h[8]; uint4 v; } u;
    u.h[0] = __float2bfloat16(a.x); u.h[1] = __float2bfloat16(a.y);
    u.h[2] = __float2bfloat16(a.z); u.h[3] = __float2bfloat16(a.w);
    u.h[4] = __float2bfloat16(b.x); u.h[5] = __float2bfloat16(b.y);
    u.h[6] = __float2bfloat16(b.z); u.h[7] = __float2bfloat16(b.w);
    *(uint4*)(out + base) = u.v;
}

// ---------------- grid barrier ----------------------------------------------
__device__ __forceinline__ void grid_barrier(unsigned nb) {
    __syncthreads();
    if (threadIdx.x == 0) {
        unsigned gen = g_bar_gen;
        __threadfence();
        if (atomicAdd(&g_bar_count, 1u) == nb - 1u) {
            g_bar_count = 0u;
            __threadfence();
            g_bar_gen = gen + 1u;
        } else {
            while (g_bar_gen == gen) { __nanosleep(64); }
            __threadfence();
        }
    }
    __syncthreads();
}

// ---------------- persistent bidirectional LSTM (HMMA recurrence) -----------
// 128 CTAs: dir = bid>>6, chunk = bid&63 -> 8 h-dims. Per step:
//   gates[32 gate-rows x 32 batch] = W[32 x 512] @ h[32 x 512]^T via
//   m16n8k16 bf16 HMMA, K split across 8 warps (64 each), W frags preloaded
//   in registers. h staged bf16 into 1040B-padded smem rows (conflict-free
//   ldmatrix). Partials reduced through smem, gates in fp32.
#define HROWB 1040                          // bytes per padded bf16 row (520 elems)
#define LSTM_W_BYTES  (32 * HROWB)          // 33280
#define LSTM_H_BYTES  (32 * HROWB)          // 33280
#define LSTM_PSUM_BYTES (8 * 32 * 33 * 4)   // 33792
#define LSTM_GPRE_BYTES (32 * 33 * 4)       // 4224
#define LSTM_C_BYTES  (32 * 8 * 4)          // 1024
#define LSTM_SMEM_BYTES (LSTM_W_BYTES + LSTM_H_BYTES + LSTM_PSUM_BYTES + LSTM_GPRE_BYTES + LSTM_C_BYTES)

__global__ void __launch_bounds__(256, 1)
lstm_kernel(const __nv_bfloat16* __restrict__ W_hh_f_bf,
            const __nv_bfloat16* __restrict__ W_hh_b_bf)
{
    extern __shared__ __align__(1024) char smc[];
    __nv_bfloat16* Wsh = (__nv_bfloat16*)smc;                    // 32 rows x 1040B
    __nv_bfloat16* hsh = (__nv_bfloat16*)(smc + LSTM_W_BYTES);   // 32 rows x 1040B
    float* psum = (float*)(smc + LSTM_W_BYTES + LSTM_H_BYTES);   // [8][32][33]
    float* gpre = psum + 8 * 32 * 33;                            // [32][33]
    float* csh  = gpre + 32 * 33;                                // [32][8]
    const uint32_t WshU = smem_to_u32(Wsh);
    const uint32_t hshU = smem_to_u32(hsh);

    const int tid   = threadIdx.x;
    const int lane  = tid & 31;
    const int ks    = tid >> 5;              // warp id = K-slice 0..7
    const int dir   = blockIdx.x >> 6;
    const int chunk = blockIdx.x & 63;
    const int j0    = chunk * 8;
    const float* xg  = dir ? g_xgb : g_xgf;
    const __nv_bfloat16* Whh = dir ? W_hh_b_bf : W_hh_f_bf;
    float* hs        = dir ? g_hb : g_hf;

    // ---- load W slice (bf16) into padded smem rows ----
    // Wsh row m (0..31) = global row (m>>3)*512 + j0 + (m&7); 512 bf16 = 64x16B
    for (int v = tid; v < 32 * 64; v += 256) {
        int m = v >> 6, c = v & 63;
        int grow = ((m >> 3) << 9) + j0 + (m & 7);
        uint4 w = *(const uint4*)(Whh + (size_t)grow * Hn + c * 8);
        *(uint4*)((char*)Wsh + m * HROWB + c * 16) = w;
    }
    {
        int b = tid >> 3, jj = tid & 7;
        csh[b * 8 + jj] = 0.f;
        g_hping_bf[dir][0][b * Hn + j0 + jj] = __float2bfloat16(0.f);
    }
    __syncthreads();

    // ---- preload A (W) fragments: warp ks covers k in [ks*64, ks*64+64) ----
    uint32_t afr[2][4][4];   // [m-tile][k16 step][frag]
    {
        const int aRow = lane & 15;
        const int aColB = ks * 128 + (lane >> 4) * 16;
#pragma unroll
        for (int mi = 0; mi < 2; mi++)
#pragma unroll
            for (int kk = 0; kk < 4; kk++)
                ldsm_x4(WshU + (mi * 16 + aRow) * HROWB + aColB + kk * 32,
                        afr[mi][kk][0], afr[mi][kk][1], afr[mi][kk][2], afr[mi][kk][3]);
    }
    grid_barrier(128);

    const int bRowBase = (lane & 7) + ((lane >> 4) << 3);
    const int bColB = ks * 128 + (((lane >> 3) & 1) << 4);
    const int qrow = lane >> 2;
    const int qcol = (lane & 3) * 2;

    for (int t = 0; t < Tn; t++) {
        const int p = t & 1;
        const int tact = dir ? (Tn - 1 - t) : t;

        // ---- stage h (bf16, 32x512) into padded smem rows via cp.async ----
        const __nv_bfloat16* hg = g_hping_bf[dir][p];
#pragma unroll
        for (int u = 0; u < 8; u++) {
            int idx = tid + u * 256;       // 0..2047
            int b = idx >> 6, c = idx & 63;
            cp_async16(hshU + b * HROWB + c * 16, hg + b * Hn + c * 8);
        }
        CP_COMMIT();
        CP_WAIT_0();
        __syncthreads();

        // ---- HMMA: gates[32x32] partial for this K-slice ----
        float d[2][4][4];
#pragma unroll
        for (int mi = 0; mi < 2; mi++)
#pragma unroll
            for (int ni = 0; ni < 4; ni++)
#pragma unroll
                for (int q = 0; q < 4; q++) d[mi][ni][q] = 0.f;

#pragma unroll
        for (int kk = 0; kk < 4; kk++) {
            uint32_t bfr[4][2];
#pragma unroll
            for (int nt = 0; nt < 2; nt++) {
                uint32_t r0, r1, r2, r3;
                ldsm_x4(hshU + (bRowBase + nt * 16) * HROWB + bColB + kk * 32,
                        r0, r1, r2, r3);
                bfr[nt * 2][0] = r0; bfr[nt * 2][1] = r1;
                bfr[nt * 2 + 1][0] = r2; bfr[nt * 2 + 1][1] = r3;
            }
#pragma unroll
            for (int mi = 0; mi < 2; mi++)
#pragma unroll
                for (int ni = 0; ni < 4; ni++)
                    mma16816(d[mi][ni], afr[mi][kk], bfr[ni]);
        }

        // ---- partials -> smem ----
#pragma unroll
        for (int mi = 0; mi < 2; mi++)
#pragma unroll
            for (int ni = 0; ni < 4; ni++) {
                int r = mi * 16 + qrow;
                int c = ni * 8 + qcol;
                psum[(ks * 32 + r) * 33 + c]       = d[mi][ni][0];
                psum[(ks * 32 + r) * 33 + c + 1]   = d[mi][ni][1];
                psum[(ks * 32 + r + 8) * 33 + c]     = d[mi][ni][2];
                psum[(ks * 32 + r + 8) * 33 + c + 1] = d[mi][ni][3];
            }
        __syncthreads();

        // ---- reduce over 8 K-slices ----
#pragma unroll
        for (int u = 0; u < 4; u++) {
            int idx = tid + u * 256;      // 0..1023
            int r = idx >> 5, b = idx & 31;
            float s = 0.f;
#pragma unroll
            for (int kk = 0; kk < 8; kk++) s += psum[(kk * 32 + r) * 33 + b];
            gpre[r * 33 + b] = s;
        }
        __syncthreads();

        // ---- gate update ----
        {
            int b = tid >> 3, jj = tid & 7;
            size_t xbase = ((size_t)tact * Bn + b) * FOURH + j0 + jj;
            float gi = gpre[(jj) * 33 + b]      + xg[xbase];
            float gf = gpre[(8 + jj) * 33 + b]  + xg[xbase + 512];
            float gg = gpre[(16 + jj) * 33 + b] + xg[xbase + 1024];
            float go = gpre[(24 + jj) * 33 + b] + xg[xbase + 1536];
            float iv = 1.f / (1.f + expf(-gi));
            float fv = 1.f / (1.f + expf(-gf));
            float gv = tanhf(gg);
            float ov = 1.f / (1.f + expf(-go));
            float c = fv * csh[b * 8 + jj] + iv * gv;
            csh[b * 8 + jj] = c;
            float h = ov * tanhf(c);
            g_hping_bf[dir][p ^ 1][b * Hn + j0 + jj] = __float2bfloat16(h);
            hs[((size_t)tact * Bn + b) * Hn + j0 + jj] = h;
        }
        grid_barrier(128);
    }
}

// ---------------- feats: warp per (t,b) -------------------------------------
__global__ void __launch_bounds__(128)
feats_kernel(const float* __restrict__ W_lin, const float* __restrict__ b_lin)
{
    int warp = threadIdx.x >> 5, lane = threadIdx.x & 31;
    int idx = blockIdx.x * 4 + warp;
    int t = idx >> 5, b = idx & 31;
    const float* hfp = g_hf + (size_t)idx * Hn;
    const float* hbp = g_hb + (size_t)idx * Hn;

    float hreg[16], hbreg[16];
#pragma unroll
    for (int i = 0; i < 16; i++) {
        hreg[i]  = hfp[lane + 32 * i];
        hbreg[i] = hbp[lane + 32 * i];
    }
    for (int k = 0; k < Kc; k++) {
        const float* wl = W_lin + k * (2 * Hn);
        float s = 0.f;
#pragma unroll
        for (int i = 0; i < 16; i++) {
            s += hreg[i]  * wl[lane + 32 * i];
            s += hbreg[i] * wl[512 + lane + 32 * i];
        }
#pragma unroll
        for (int o = 16; o; o >>= 1) s += __shfl_xor_sync(0xffffffffu, s, o);
        if (lane == 0)
            g_feats[((size_t)b * Tn + t) * Kc + k] = s + b_lin[k];
    }
}

// ---------------- CRF: warp per batch ---------------------------------------
__global__ void __launch_bounds__(32)
crf_kernel(const int* __restrict__ tags, const float* __restrict__ trans,
           float* __restrict__ out)
{
    int b = blockIdx.x, lane = threadIdx.x;
    float tr[Kc];
#pragma unroll
    for (int j = 0; j < Kc; j++)
        tr[j] = (lane < Kc) ? trans[lane * Kc + j] : 0.f;

    float alpha = (lane == START_TAG) ? 0.f : -10000.f;
    const float* fb = g_feats + (size_t)b * Tn * Kc;

    for (int t = 0; t < Tn; t++) {
        float m = -3.4e38f, s = 0.f;
#pragma unroll
        for (int j = 0; j < Kc; j++) {
            float aj = __shfl_sync(0xffffffffu, alpha, j);
            float v = aj + tr[j];
            if (v > m) { s = s * expf(m - v) + 1.f; m = v; }
            else       { s += expf(v - m); }
        }
        float e = (lane < Kc) ? fb[t * Kc + lane] : 0.f;
        alpha = m + logf(s) + e;
        if (lane >= Kc) alpha = -3.4e38f;
    }

    float v = (lane < Kc) ? alpha + trans[STOP_TAG * Kc + lane] : -3.4e38f;
    float m = v;
#pragma unroll
    for (int o = 16; o; o >>= 1) m = fmaxf(m, __shfl_xor_sync(0xffffffffu, m, o));
    float se = (lane < Kc) ? expf(v - m) : 0.f;
#pragma unroll
    for (int o = 16; o; o >>= 1) se += __shfl_xor_sync(0xffffffffu, se, o);
    float logZ = m + logf(se);

    const int* tg = tags + b * Tn;
    float ts = 0.f, es = 0.f;
    for (int t = lane; t < Tn; t += 32) {
        int nxt = tg[t];
        int prev = (t == 0) ? START_TAG : tg[t - 1];
        ts += trans[nxt * Kc + prev];
        es += fb[t * Kc + nxt];
    }
    if (lane == 0) ts += trans[STOP_TAG * Kc + tg[Tn - 1]];
#pragma unroll
    for (int o = 16; o; o >>= 1) {
        ts += __shfl_xor_sync(0xffffffffu, ts, o);
        es += __shfl_xor_sync(0xffffffffu, es, o);
    }
    if (lane == 0) out[b] = logZ - (ts + es);
}

// ---------------- launch -----------------------------------------------------
extern "C" void kernel_launch(void* const* d_in, const int* in_sizes, int n_in,
                              void* d_out, int out_size)
{
    const float* x      = (const float*)d_in[0];
    const int*   tags   = (const int*)d_in[1];
    const float* W_e2n  = (const float*)d_in[2];
    const float* b_e2n  = (const float*)d_in[3];
    const float* W_ih_f = (const float*)d_in[4];
    const float* W_hh_f = (const float*)d_in[5];
    const float* b_f    = (const float*)d_in[6];
    const float* W_ih_b = (const float*)d_in[7];
    const float* W_hh_b = (const float*)d_in[8];
    const float* b_b    = (const float*)d_in[9];
    const float* W_lin  = (const float*)d_in[10];
    const float* b_lin  = (const float*)d_in[11];
    const float* trans  = (const float*)d_in[12];
    float* out = (float*)d_out;

    __nv_bfloat16 *xbf, *we2nbf, *xnbf, *wihfbf, *wihbbf, *whhfbf, *whhbbf;
    float *xgf, *xgb;
    cudaGetSymbolAddress((void**)&xbf,    g_xbf);
    cudaGetSymbolAddress((void**)&we2nbf, g_we2n_bf);
    cudaGetSymbolAddress((void**)&xnbf,   g_xnbf);
    cudaGetSymbolAddress((void**)&wihfbf, g_wihf_bf);
    cudaGetSymbolAddress((void**)&wihbbf, g_wihb_bf);
    cudaGetSymbolAddress((void**)&whhfbf, g_whhf_bf);
    cudaGetSymbolAddress((void**)&whhbbf, g_whhb_bf);
    cudaGetSymbolAddress((void**)&xgf,    g_xgf);
    cudaGetSymbolAddress((void**)&xgb,    g_xgb);

    cudaFuncSetAttribute(lstm_kernel,
                         cudaFuncAttributeMaxDynamicSharedMemorySize,
                         LSTM_SMEM_BYTES);
    cudaFuncSetAttribute((const void*)gemm_hmma<true, false>,
                         cudaFuncAttributeMaxDynamicSharedMemorySize,
                         GEMM_SMEM_BYTES);
    cudaFuncSetAttribute((const void*)gemm_hmma<false, true>,
                         cudaFuncAttributeMaxDynamicSharedMemorySize,
                         GEMM_SMEM_BYTES);

    // 0) fp32 -> bf16 conversions
    cvt_f32_bf16<<<(TB * En) / (256 * 8), 256>>>(x, xbf, TB * En);
    cvt_f32_bf16<<<(En * En) / (256 * 8), 256>>>(W_e2n, we2nbf, En * En);
    cvt_f32_bf16<<<(FOURH * En) / (256 * 8), 256>>>(W_ih_f, wihfbf, FOURH * En);
    cvt_f32_bf16<<<(FOURH * En) / (256 * 8), 256>>>(W_ih_b, wihbbf, FOURH * En);
    cvt_f32_bf16<<<(FOURH * Hn) / (256 * 8), 256>>>(W_hh_f, whhfbf, FOURH * Hn);
    cvt_f32_bf16<<<(FOURH * Hn) / (256 * 8), 256>>>(W_hh_b, whhbbf, FOURH * Hn);

    // 1) xn = x @ W_e2n^T + b_e2n  (bf16 out)
    {
        dim3 grid(En / 128, TB / 128);
        gemm_hmma<true, false><<<grid, 256, GEMM_SMEM_BYTES>>>(
            xbf, we2nbf, nullptr, b_e2n, nullptr, xnbf, nullptr, TB, En, En, 0);
    }
    // 2) xg_f / xg_b = xn @ W_ih^T + b  (fp32 out; one fused launch)
    {
        dim3 grid(2 * (FOURH / 128), TB / 128);
        gemm_hmma<false, true><<<grid, 256, GEMM_SMEM_BYTES>>>(
            xnbf, wihfbf, wihbbf, b_f, b_b, xgf, xgb, TB, FOURH, En, FOURH / 128);
    }
    // 3) bidirectional LSTM scan (HMMA recurrence)
    lstm_kernel<<<128, 256, LSTM_SMEM_BYTES>>>(whhfbf, whhbbf);

    // 4) feats
    feats_kernel<<<TB / 4, 128>>>(W_lin, b_lin);

    // 5) CRF
    crf_kernel<<<Bn, 32>>>(tags, trans, out);
}

// round 5
// speedup vs baseline: 4.7573x; 1.0488x over previous
#include <cuda_runtime.h>
#include <cuda_bf16.h>
#include <math.h>
#include <stdint.h>

// ---------------- problem constants ----------------
#define Tn 128
#define Bn 32
#define En 4096
#define Hn 512
#define FOURH 2048
#define TB 4096          // T*B
#define Kc 20
#define START_TAG 18
#define STOP_TAG 19

// ---------------- scratch (device globals; allocation-free) ----------------
__device__ __align__(256) __nv_bfloat16 g_xbf[(size_t)TB * En];
__device__ __align__(256) __nv_bfloat16 g_we2n_bf[(size_t)En * En];
__device__ __align__(256) __nv_bfloat16 g_xnbf[(size_t)TB * En];
__device__ __align__(256) __nv_bfloat16 g_wihf_bf[(size_t)FOURH * En];
__device__ __align__(256) __nv_bfloat16 g_wihb_bf[(size_t)FOURH * En];
__device__ __align__(256) __nv_bfloat16 g_whhf_bf[(size_t)FOURH * Hn];
__device__ __align__(256) __nv_bfloat16 g_whhb_bf[(size_t)FOURH * Hn];
__device__ float g_xgf[(size_t)TB * FOURH];
__device__ float g_xgb[(size_t)TB * FOURH];
__device__ float g_hf[(size_t)TB * Hn];
__device__ float g_hb[(size_t)TB * Hn];
__device__ __align__(256) __nv_bfloat16 g_hping_bf[2][2][Bn * Hn];
__device__ float g_feats[(size_t)Bn * Tn * Kc];

__device__ unsigned g_bar2[2] = {0u, 0u};
__device__ volatile unsigned g_gen2[2] = {0u, 0u};

// ================= helpers ===================================================
__device__ __forceinline__ uint32_t smem_to_u32(const void* p) {
    uint32_t a;
    asm("{ .reg .u64 t; cvta.to.shared.u64 t, %1; cvt.u32.u64 %0, t; }"
        : "=r"(a) : "l"(p));
    return a;
}
#define SW128(o) ((o) ^ (((o) >> 3) & 0x70))

__device__ __forceinline__ void cp_async16(uint32_t dst, const void* src) {
    asm volatile("cp.async.cg.shared.global [%0], [%1], 16;" :: "r"(dst), "l"(src));
}
#define CP_COMMIT() asm volatile("cp.async.commit_group;" ::: "memory")
#define CP_WAIT_1() asm volatile("cp.async.wait_group 1;" ::: "memory")
#define CP_WAIT_0() asm volatile("cp.async.wait_group 0;" ::: "memory")

__device__ __forceinline__ void ldsm_x4(uint32_t addr, uint32_t& r0, uint32_t& r1,
                                        uint32_t& r2, uint32_t& r3) {
    asm volatile("ldmatrix.sync.aligned.m8n8.x4.shared.b16 {%0,%1,%2,%3}, [%4];"
                 : "=r"(r0), "=r"(r1), "=r"(r2), "=r"(r3) : "r"(addr));
}

__device__ __forceinline__ void mma16816(float* d, const uint32_t* a, const uint32_t* b) {
    asm volatile(
        "mma.sync.aligned.m16n8k16.row.col.f32.bf16.bf16.f32 "
        "{%0,%1,%2,%3}, {%4,%5,%6,%7}, {%8,%9}, {%0,%1,%2,%3};"
        : "+f"(d[0]), "+f"(d[1]), "+f"(d[2]), "+f"(d[3])
        : "r"(a[0]), "r"(a[1]), "r"(a[2]), "r"(a[3]), "r"(b[0]), "r"(b[1]));
}

// ================= HMMA GEMM: C[M,N] = A[M,K]bf16 @ B[N,K]bf16^T + bias ======
// CTA tile 128(M) x 256(N), K-step 64, 3-stage cp.async, 512 threads.
// 16 warps: warp_m = wid&3 (m: 32), warp_n = wid>>2 (n: 64). Warp tile 32x64.
#define GSTAGE_BYTES 49152                  // A 16KB + B 32KB
#define GEMM_SMEM_BYTES (3 * GSTAGE_BYTES)  // 144KB

template <bool OUT_BF16, bool DUAL>
__global__ void __launch_bounds__(512)
gemm_hmma(const __nv_bfloat16* __restrict__ Aq, const __nv_bfloat16* __restrict__ Bq0,
          const __nv_bfloat16* __restrict__ Bq1,
          const float* __restrict__ bias0, const float* __restrict__ bias1,
          void* __restrict__ Cout0, void* __restrict__ Cout1,
          int M, int N, int K, int nbx)
{
    extern __shared__ __align__(1024) char smem[];
    const uint32_t sb = smem_to_u32(smem);

    const int tid = threadIdx.x;
    const int wid = tid >> 5;
    const int lane = tid & 31;
    const int warp_m = wid & 3;
    const int warp_n = wid >> 2;            // 0..3
    int bx = blockIdx.x;
    const __nv_bfloat16* Bq = Bq0;
    const float* bias = bias0;
    void* Cout = Cout0;
    if (DUAL && bx >= nbx) {
        bx -= nbx; Bq = Bq1; bias = bias1; Cout = Cout1;
    }
    const int m0 = blockIdx.y * 128;
    const int n0 = bx * 256;
    const int NKT = K / 64;

    const int ldr = tid >> 3;               // 0..63
    const int ldc = tid & 7;

#define G_LOAD(kt) do { \
        if ((kt) < NKT) { \
            const uint32_t st = sb + ((kt) % 3) * GSTAGE_BYTES; \
            int _k0 = (kt) * 64; \
            _Pragma("unroll") \
            for (int _p = 0; _p < 2; _p++) { \
                int _r = ldr + _p * 64; \
                cp_async16(st + SW128(_r * 128 + ldc * 16), \
                           Aq + (size_t)(m0 + _r) * K + _k0 + ldc * 8); \
            } \
            _Pragma("unroll") \
            for (int _p = 0; _p < 4; _p++) { \
                int _r = ldr + _p * 64; \
                cp_async16(st + 16384 + SW128(_r * 128 + ldc * 16), \
                           Bq + (size_t)(n0 + _r) * K + _k0 + ldc * 8); \
            } \
        } \
        CP_COMMIT(); \
    } while (0)

    float d[2][8][4];
#pragma unroll
    for (int mi = 0; mi < 2; mi++)
#pragma unroll
        for (int ni = 0; ni < 8; ni++)
#pragma unroll
            for (int q = 0; q < 4; q++) d[mi][ni][q] = 0.f;

    const int aRow = warp_m * 32 + (lane & 15);
    const int aColB = (lane >> 4) * 16;
    const int bRow = warp_n * 64 + (lane & 7) + (lane >> 4) * 8;
    const int bColB = ((lane >> 3) & 1) * 16;

    G_LOAD(0);
    G_LOAD(1);

    for (int i = 0; i < NKT; i++) {
        CP_WAIT_1();
        __syncthreads();
        G_LOAD(i + 2);

        const uint32_t stA = sb + (i % 3) * GSTAGE_BYTES;
        const uint32_t stB = stA + 16384;
#pragma unroll
        for (int ks = 0; ks < 4; ks++) {
            const int kb = ks * 32;
            uint32_t a[2][4];
#pragma unroll
            for (int mi = 0; mi < 2; mi++)
                ldsm_x4(stA + SW128((aRow + mi * 16) * 128 + kb + aColB),
                        a[mi][0], a[mi][1], a[mi][2], a[mi][3]);
            uint32_t b[8][2];
#pragma unroll
            for (int np = 0; np < 4; np++) {
                uint32_t r0, r1, r2, r3;
                ldsm_x4(stB + SW128((bRow + np * 16) * 128 + kb + bColB),
                        r0, r1, r2, r3);
                b[np * 2][0] = r0; b[np * 2][1] = r1;
                b[np * 2 + 1][0] = r2; b[np * 2 + 1][1] = r3;
            }
#pragma unroll
            for (int mi = 0; mi < 2; mi++)
#pragma unroll
                for (int ni = 0; ni < 8; ni++)
                    mma16816(d[mi][ni], a[mi], b[ni]);
        }
    }

    const int qrow = lane >> 2;
    const int qcol = (lane & 3) * 2;
#pragma unroll
    for (int mi = 0; mi < 2; mi++) {
#pragma unroll
        for (int ni = 0; ni < 8; ni++) {
            const int col = n0 + warp_n * 64 + ni * 8 + qcol;
            const int row = m0 + warp_m * 32 + mi * 16 + qrow;
            const float b0 = bias[col], b1 = bias[col + 1];
            float v00 = d[mi][ni][0] + b0, v01 = d[mi][ni][1] + b1;
            float v10 = d[mi][ni][2] + b0, v11 = d[mi][ni][3] + b1;
            if (OUT_BF16) {
                __nv_bfloat16* C = (__nv_bfloat16*)Cout;
                __nv_bfloat162 p0 = __floats2bfloat162_rn(v00, v01);
                __nv_bfloat162 p1 = __floats2bfloat162_rn(v10, v11);
                *(__nv_bfloat162*)(C + (size_t)row * N + col) = p0;
                *(__nv_bfloat162*)(C + (size_t)(row + 8) * N + col) = p1;
            } else {
                float* C = (float*)Cout;
                *(float2*)(C + (size_t)row * N + col) = make_float2(v00, v01);
                *(float2*)(C + (size_t)(row + 8) * N + col) = make_float2(v10, v11);
            }
        }
    }
}

// ================= fp32 -> bf16 conversion ===================================
__global__ void __launch_bounds__(256)
cvt_f32_bf16(const float* __restrict__ in, __nv_bfloat16* __restrict__ out, int n)
{
    int base = (blockIdx.x * 256 + threadIdx.x) * 8;
    if (base >= n) return;
    float4 a = *(const float4*)(in + base);
    float4 b = *(const float4*)(in + base + 4);
    union { __nv_bfloat16 h[8]; uint4 v; } u;
    u.h[0] = __float2bfloat16(a.x); u.h[1] = __float2bfloat16(a.y);
    u.h[2] = __float2bfloat16(a.z); u.h[3] = __float2bfloat16(a.w);
    u.h[4] = __float2bfloat16(b.x); u.h[5] = __float2bfloat16(b.y);
    u.h[6] = __float2bfloat16(b.z); u.h[7] = __float2bfloat16(b.w);
    *(uint4*)(out + base) = u.v;
}

// ---------------- per-direction grid barrier (64 CTAs each) -----------------
__device__ __forceinline__ void grid_barrier_dir(int dir) {
    __syncthreads();
    if (threadIdx.x == 0) {
        unsigned gen = g_gen2[dir];
        __threadfence();
        if (atomicAdd(&g_bar2[dir], 1u) == 63u) {
            g_bar2[dir] = 0u;
            __threadfence();
            g_gen2[dir] = gen + 1u;
        } else {
            while (g_gen2[dir] == gen) { }
            __threadfence();
        }
    }
    __syncthreads();
}

// ---------------- persistent bidirectional LSTM (HMMA recurrence) -----------
#define HROWB 1040
#define LSTM_W_BYTES  (32 * HROWB)
#define LSTM_H_BYTES  (32 * HROWB)
#define LSTM_PSUM_BYTES (8 * 32 * 33 * 4)
#define LSTM_GPRE_BYTES (32 * 33 * 4)
#define LSTM_C_BYTES  (32 * 8 * 4)
#define LSTM_SMEM_BYTES (LSTM_W_BYTES + LSTM_H_BYTES + LSTM_PSUM_BYTES + LSTM_GPRE_BYTES + LSTM_C_BYTES)

__global__ void __launch_bounds__(256, 1)
lstm_kernel(const __nv_bfloat16* __restrict__ W_hh_f_bf,
            const __nv_bfloat16* __restrict__ W_hh_b_bf)
{
    extern __shared__ __align__(1024) char smc[];
    __nv_bfloat16* Wsh = (__nv_bfloat16*)smc;
    __nv_bfloat16* hsh = (__nv_bfloat16*)(smc + LSTM_W_BYTES);
    float* psum = (float*)(smc + LSTM_W_BYTES + LSTM_H_BYTES);
    float* gpre = psum + 8 * 32 * 33;
    float* csh  = gpre + 32 * 33;
    const uint32_t WshU = smem_to_u32(Wsh);
    const uint32_t hshU = smem_to_u32(hsh);

    const int tid   = threadIdx.x;
    const int lane  = tid & 31;
    const int ks    = tid >> 5;
    const int dir   = blockIdx.x >> 6;
    const int chunk = blockIdx.x & 63;
    const int j0    = chunk * 8;
    const float* xg  = dir ? g_xgb : g_xgf;
    const __nv_bfloat16* Whh = dir ? W_hh_b_bf : W_hh_f_bf;
    float* hs        = dir ? g_hb : g_hf;

    for (int v = tid; v < 32 * 64; v += 256) {
        int m = v >> 6, c = v & 63;
        int grow = ((m >> 3) << 9) + j0 + (m & 7);
        uint4 w = *(const uint4*)(Whh + (size_t)grow * Hn + c * 8);
        *(uint4*)((char*)Wsh + m * HROWB + c * 16) = w;
    }
    {
        int b = tid >> 3, jj = tid & 7;
        csh[b * 8 + jj] = 0.f;
        g_hping_bf[dir][0][b * Hn + j0 + jj] = __float2bfloat16(0.f);
    }
    __syncthreads();

    uint32_t afr[2][4][4];
    {
        const int aRow = lane & 15;
        const int aColB = ks * 128 + (lane >> 4) * 16;
#pragma unroll
        for (int mi = 0; mi < 2; mi++)
#pragma unroll
            for (int kk = 0; kk < 4; kk++)
                ldsm_x4(WshU + (mi * 16 + aRow) * HROWB + aColB + kk * 32,
                        afr[mi][kk][0], afr[mi][kk][1], afr[mi][kk][2], afr[mi][kk][3]);
    }
    grid_barrier_dir(dir);

    const int bRowBase = (lane & 7) + ((lane >> 4) << 3);
    const int bColB = ks * 128 + (((lane >> 3) & 1) << 4);
    const int qrow = lane >> 2;
    const int qcol = (lane & 3) * 2;

    for (int t = 0; t < Tn; t++) {
        const int p = t & 1;
        const int tact = dir ? (Tn - 1 - t) : t;

        const __nv_bfloat16* hg = g_hping_bf[dir][p];
#pragma unroll
        for (int u = 0; u < 8; u++) {
            int idx = tid + u * 256;
            int b = idx >> 6, c = idx & 63;
            cp_async16(hshU + b * HROWB + c * 16, hg + b * Hn + c * 8);
        }
        CP_COMMIT();
        CP_WAIT_0();
        __syncthreads();

        float d[2][4][4];
#pragma unroll
        for (int mi = 0; mi < 2; mi++)
#pragma unroll
            for (int ni = 0; ni < 4; ni++)
#pragma unroll
                for (int q = 0; q < 4; q++) d[mi][ni][q] = 0.f;

#pragma unroll
        for (int kk = 0; kk < 4; kk++) {
            uint32_t bfr[4][2];
#pragma unroll
            for (int nt = 0; nt < 2; nt++) {
                uint32_t r0, r1, r2, r3;
                ldsm_x4(hshU + (bRowBase + nt * 16) * HROWB + bColB + kk * 32,
                        r0, r1, r2, r3);
                bfr[nt * 2][0] = r0; bfr[nt * 2][1] = r1;
                bfr[nt * 2 + 1][0] = r2; bfr[nt * 2 + 1][1] = r3;
            }
#pragma unroll
            for (int mi = 0; mi < 2; mi++)
#pragma unroll
                for (int ni = 0; ni < 4; ni++)
                    mma16816(d[mi][ni], afr[mi][kk], bfr[ni]);
        }

#pragma unroll
        for (int mi = 0; mi < 2; mi++)
#pragma unroll
            for (int ni = 0; ni < 4; ni++) {
                int r = mi * 16 + qrow;
                int c = ni * 8 + qcol;
                psum[(ks * 32 + r) * 33 + c]       = d[mi][ni][0];
                psum[(ks * 32 + r) * 33 + c + 1]   = d[mi][ni][1];
                psum[(ks * 32 + r + 8) * 33 + c]     = d[mi][ni][2];
                psum[(ks * 32 + r + 8) * 33 + c + 1] = d[mi][ni][3];
            }
        __syncthreads();

#pragma unroll
        for (int u = 0; u < 4; u++) {
            int idx = tid + u * 256;
            int r = idx >> 5, b = idx & 31;
            float s = 0.f;
#pragma unroll
            for (int kk = 0; kk < 8; kk++) s += psum[(kk * 32 + r) * 33 + b];
            gpre[r * 33 + b] = s;
        }
        __syncthreads();

        {
            int b = tid >> 3, jj = tid & 7;
            size_t xbase = ((size_t)tact * Bn + b) * FOURH + j0 + jj;
            float gi = gpre[(jj) * 33 + b]      + xg[xbase];
            float gf = gpre[(8 + jj) * 33 + b]  + xg[xbase + 512];
            float gg = gpre[(16 + jj) * 33 + b] + xg[xbase + 1024];
            float go = gpre[(24 + jj) * 33 + b] + xg[xbase + 1536];
            float iv = 1.f / (1.f + expf(-gi));
            float fv = 1.f / (1.f + expf(-gf));
            float gv = tanhf(gg);
            float ov = 1.f / (1.f + expf(-go));
            float c = fv * csh[b * 8 + jj] + iv * gv;
            csh[b * 8 + jj] = c;
            float h = ov * tanhf(c);
            g_hping_bf[dir][p ^ 1][b * Hn + j0 + jj] = __float2bfloat16(h);
            hs[((size_t)tact * Bn + b) * Hn + j0 + jj] = h;
        }
        grid_barrier_dir(dir);
    }
}

// ---------------- feats: warp per (t,b) -------------------------------------
__global__ void __launch_bounds__(128)
feats_kernel(const float* __restrict__ W_lin, const float* __restrict__ b_lin)
{
    int warp = threadIdx.x >> 5, lane = threadIdx.x & 31;
    int idx = blockIdx.x * 4 + warp;
    int t = idx >> 5, b = idx & 31;
    const float* hfp = g_hf + (size_t)idx * Hn;
    const float* hbp = g_hb + (size_t)idx * Hn;

    float hreg[16], hbreg[16];
#pragma unroll
    for (int i = 0; i < 16; i++) {
        hreg[i]  = hfp[lane + 32 * i];
        hbreg[i] = hbp[lane + 32 * i];
    }
    for (int k = 0; k < Kc; k++) {
        const float* wl = W_lin + k * (2 * Hn);
        float s = 0.f;
#pragma unroll
        for (int i = 0; i < 16; i++) {
            s += hreg[i]  * wl[lane + 32 * i];
            s += hbreg[i] * wl[512 + lane + 32 * i];
        }
#pragma unroll
        for (int o = 16; o; o >>= 1) s += __shfl_xor_sync(0xffffffffu, s, o);
        if (lane == 0)
            g_feats[((size_t)b * Tn + t) * Kc + k] = s + b_lin[k];
    }
}

// ---------------- CRF: warp per batch ---------------------------------------
__global__ void __launch_bounds__(32)
crf_kernel(const int* __restrict__ tags, const float* __restrict__ trans,
           float* __restrict__ out)
{
    int b = blockIdx.x, lane = threadIdx.x;
    float tr[Kc];
#pragma unroll
    for (int j = 0; j < Kc; j++)
        tr[j] = (lane < Kc) ? trans[lane * Kc + j] : 0.f;

    float alpha = (lane == START_TAG) ? 0.f : -10000.f;
    const float* fb = g_feats + (size_t)b * Tn * Kc;

    for (int t = 0; t < Tn; t++) {
        float v[Kc];
#pragma unroll
        for (int j = 0; j < Kc; j++)
            v[j] = __shfl_sync(0xffffffffu, alpha, j) + tr[j];
        float m = v[0];
#pragma unroll
        for (int j = 1; j < Kc; j++) m = fmaxf(m, v[j]);
        float s = 0.f;
#pragma unroll
        for (int j = 0; j < Kc; j++) s += expf(v[j] - m);
        float e = (lane < Kc) ? fb[t * Kc + lane] : 0.f;
        alpha = m + logf(s) + e;
        if (lane >= Kc) alpha = -3.4e38f;
    }

    float v = (lane < Kc) ? alpha + trans[STOP_TAG * Kc + lane] : -3.4e38f;
    float m = v;
#pragma unroll
    for (int o = 16; o; o >>= 1) m = fmaxf(m, __shfl_xor_sync(0xffffffffu, m, o));
    float se = (lane < Kc) ? expf(v - m) : 0.f;
#pragma unroll
    for (int o = 16; o; o >>= 1) se += __shfl_xor_sync(0xffffffffu, se, o);
    float logZ = m + logf(se);

    const int* tg = tags + b * Tn;
    float ts = 0.f, es = 0.f;
    for (int t = lane; t < Tn; t += 32) {
        int nxt = tg[t];
        int prev = (t == 0) ? START_TAG : tg[t - 1];
        ts += trans[nxt * Kc + prev];
        es += fb[t * Kc + nxt];
    }
    if (lane == 0) ts += trans[STOP_TAG * Kc + tg[Tn - 1]];
#pragma unroll
    for (int o = 16; o; o >>= 1) {
        ts += __shfl_xor_sync(0xffffffffu, ts, o);
        es += __shfl_xor_sync(0xffffffffu, es, o);
    }
    if (lane == 0) out[b] = logZ - (ts + es);
}

// ---------------- launch -----------------------------------------------------
extern "C" void kernel_launch(void* const* d_in, const int* in_sizes, int n_in,
                              void* d_out, int out_size)
{
    const float* x      = (const float*)d_in[0];
    const int*   tags   = (const int*)d_in[1];
    const float* W_e2n  = (const float*)d_in[2];
    const float* b_e2n  = (const float*)d_in[3];
    const float* W_ih_f = (const float*)d_in[4];
    const float* W_hh_f = (const float*)d_in[5];
    const float* b_f    = (const float*)d_in[6];
    const float* W_ih_b = (const float*)d_in[7];
    const float* W_hh_b = (const float*)d_in[8];
    const float* b_b    = (const float*)d_in[9];
    const float* W_lin  = (const float*)d_in[10];
    const float* b_lin  = (const float*)d_in[11];
    const float* trans  = (const float*)d_in[12];
    float* out = (float*)d_out;

    __nv_bfloat16 *xbf, *we2nbf, *xnbf, *wihfbf, *wihbbf, *whhfbf, *whhbbf;
    float *xgf, *xgb;
    cudaGetSymbolAddress((void**)&xbf,    g_xbf);
    cudaGetSymbolAddress((void**)&we2nbf, g_we2n_bf);
    cudaGetSymbolAddress((void**)&xnbf,   g_xnbf);
    cudaGetSymbolAddress((void**)&wihfbf, g_wihf_bf);
    cudaGetSymbolAddress((void**)&wihbbf, g_wihb_bf);
    cudaGetSymbolAddress((void**)&whhfbf, g_whhf_bf);
    cudaGetSymbolAddress((void**)&whhbbf, g_whhb_bf);
    cudaGetSymbolAddress((void**)&xgf,    g_xgf);
    cudaGetSymbolAddress((void**)&xgb,    g_xgb);

    cudaFuncSetAttribute(lstm_kernel,
                         cudaFuncAttributeMaxDynamicSharedMemorySize,
                         LSTM_SMEM_BYTES);
    cudaFuncSetAttribute((const void*)gemm_hmma<true, false>,
                         cudaFuncAttributeMaxDynamicSharedMemorySize,
                         GEMM_SMEM_BYTES);
    cudaFuncSetAttribute((const void*)gemm_hmma<false, true>,
                         cudaFuncAttributeMaxDynamicSharedMemorySize,
                         GEMM_SMEM_BYTES);

    // 0) fp32 -> bf16 conversions
    cvt_f32_bf16<<<(TB * En) / (256 * 8), 256>>>(x, xbf, TB * En);
    cvt_f32_bf16<<<(En * En) / (256 * 8), 256>>>(W_e2n, we2nbf, En * En);
    cvt_f32_bf16<<<(FOURH * En) / (256 * 8), 256>>>(W_ih_f, wihfbf, FOURH * En);
    cvt_f32_bf16<<<(FOURH * En) / (256 * 8), 256>>>(W_ih_b, wihbbf, FOURH * En);
    cvt_f32_bf16<<<(FOURH * Hn) / (256 * 8), 256>>>(W_hh_f, whhfbf, FOURH * Hn);
    cvt_f32_bf16<<<(FOURH * Hn) / (256 * 8), 256>>>(W_hh_b, whhbbf, FOURH * Hn);

    // 1) xn = x @ W_e2n^T + b_e2n  (bf16 out)
    {
        dim3 grid(En / 256, TB / 128);
        gemm_hmma<true, false><<<grid, 512, GEMM_SMEM_BYTES>>>(
            xbf, we2nbf, nullptr, b_e2n, nullptr, xnbf, nullptr, TB, En, En, 0);
    }
    // 2) xg_f / xg_b = xn @ W_ih^T + b  (fp32 out; one fused launch)
    {
        dim3 grid(2 * (FOURH / 256), TB / 128);
        gemm_hmma<false, true><<<grid, 512, GEMM_SMEM_BYTES>>>(
            xnbf, wihfbf, wihbbf, b_f, b_b, xgf, xgb, TB, FOURH, En, FOURH / 256);
    }
    // 3) bidirectional LSTM scan (HMMA recurrence, per-dir barriers)
    lstm_kernel<<<128, 256, LSTM_SMEM_BYTES>>>(whhfbf, whhbbf);

    // 4) feats
    feats_kernel<<<TB / 4, 128>>>(W_lin, b_lin);

    // 5) CRF
    crf_kernel<<<Bn, 32>>>(tags, trans, out);
}

// round 6
// speedup vs baseline: 4.8979x; 1.0295x over previous
#include <cuda_runtime.h>
#include <cuda_bf16.h>
#include <math.h>
#include <stdint.h>

// ---------------- problem constants ----------------
#define Tn 128
#define Bn 32
#define En 4096
#define Hn 512
#define FOURH 2048
#define TB 4096          // T*B
#define Kc 20
#define START_TAG 18
#define STOP_TAG 19

// ---------------- scratch (device globals; allocation-free) ----------------
__device__ __align__(256) __nv_bfloat16 g_xbf[(size_t)TB * En];
__device__ __align__(256) __nv_bfloat16 g_we2n_bf[(size_t)En * En];
__device__ __align__(256) __nv_bfloat16 g_xnbf[(size_t)TB * En];
__device__ __align__(256) __nv_bfloat16 g_wihf_bf[(size_t)FOURH * En];
__device__ __align__(256) __nv_bfloat16 g_wihb_bf[(size_t)FOURH * En];
__device__ __align__(256) __nv_bfloat16 g_whhf_bf[(size_t)FOURH * Hn];
__device__ __align__(256) __nv_bfloat16 g_whhb_bf[(size_t)FOURH * Hn];
__device__ __align__(256) __nv_bfloat16 g_xgf_bf[(size_t)TB * FOURH];
__device__ __align__(256) __nv_bfloat16 g_xgb_bf[(size_t)TB * FOURH];
__device__ float g_hf[(size_t)TB * Hn];
__device__ float g_hb[(size_t)TB * Hn];
__device__ __align__(256) __nv_bfloat16 g_hping_bf[2][2][Bn * Hn];
__device__ float g_feats[(size_t)Bn * Tn * Kc];

__device__ unsigned g_bar2[2] = {0u, 0u};
__device__ volatile unsigned g_gen2[2] = {0u, 0u};

// ================= helpers ===================================================
__device__ __forceinline__ uint32_t smem_to_u32(const void* p) {
    uint32_t a;
    asm("{ .reg .u64 t; cvta.to.shared.u64 t, %1; cvt.u32.u64 %0, t; }"
        : "=r"(a) : "l"(p));
    return a;
}
#define SW128(o) ((o) ^ (((o) >> 3) & 0x70))

__device__ __forceinline__ void cp_async16(uint32_t dst, const void* src) {
    asm volatile("cp.async.cg.shared.global [%0], [%1], 16;" :: "r"(dst), "l"(src));
}
#define CP_COMMIT() asm volatile("cp.async.commit_group;" ::: "memory")
#define CP_WAIT_1() asm volatile("cp.async.wait_group 1;" ::: "memory")
#define CP_WAIT_0() asm volatile("cp.async.wait_group 0;" ::: "memory")

__device__ __forceinline__ void ldsm_x4(uint32_t addr, uint32_t& r0, uint32_t& r1,
                                        uint32_t& r2, uint32_t& r3) {
    asm volatile("ldmatrix.sync.aligned.m8n8.x4.shared.b16 {%0,%1,%2,%3}, [%4];"
                 : "=r"(r0), "=r"(r1), "=r"(r2), "=r"(r3) : "r"(addr));
}

__device__ __forceinline__ void mma16816(float* d, const uint32_t* a, const uint32_t* b) {
    asm volatile(
        "mma.sync.aligned.m16n8k16.row.col.f32.bf16.bf16.f32 "
        "{%0,%1,%2,%3}, {%4,%5,%6,%7}, {%8,%9}, {%0,%1,%2,%3};"
        : "+f"(d[0]), "+f"(d[1]), "+f"(d[2]), "+f"(d[3])
        : "r"(a[0]), "r"(a[1]), "r"(a[2]), "r"(a[3]), "r"(b[0]), "r"(b[1]));
}

// ================= HMMA GEMM: C[M,N] = A[M,K]bf16 @ B[N,K]bf16^T + bias ======
// CTA tile 128(M) x 256(N), K-step 64, 3-stage cp.async, 512 threads.
#define GSTAGE_BYTES 49152                  // A 16KB + B 32KB
#define GEMM_SMEM_BYTES (3 * GSTAGE_BYTES)  // 144KB

template <bool OUT_BF16, bool DUAL>
__global__ void __launch_bounds__(512)
gemm_hmma(const __nv_bfloat16* __restrict__ Aq, const __nv_bfloat16* __restrict__ Bq0,
          const __nv_bfloat16* __restrict__ Bq1,
          const float* __restrict__ bias0, const float* __restrict__ bias1,
          void* __restrict__ Cout0, void* __restrict__ Cout1,
          int M, int N, int K, int nbx)
{
    extern __shared__ __align__(1024) char smem[];
    const uint32_t sb = smem_to_u32(smem);

    const int tid = threadIdx.x;
    const int wid = tid >> 5;
    const int lane = tid & 31;
    const int warp_m = wid & 3;
    const int warp_n = wid >> 2;            // 0..3
    int bx = blockIdx.x;
    const __nv_bfloat16* Bq = Bq0;
    const float* bias = bias0;
    void* Cout = Cout0;
    if (DUAL && bx >= nbx) {
        bx -= nbx; Bq = Bq1; bias = bias1; Cout = Cout1;
    }
    const int m0 = blockIdx.y * 128;
    const int n0 = bx * 256;
    const int NKT = K / 64;

    const int ldr = tid >> 3;               // 0..63
    const int ldc = tid & 7;

#define G_LOAD(kt) do { \
        if ((kt) < NKT) { \
            const uint32_t st = sb + ((kt) % 3) * GSTAGE_BYTES; \
            int _k0 = (kt) * 64; \
            _Pragma("unroll") \
            for (int _p = 0; _p < 2; _p++) { \
                int _r = ldr + _p * 64; \
                cp_async16(st + SW128(_r * 128 + ldc * 16), \
                           Aq + (size_t)(m0 + _r) * K + _k0 + ldc * 8); \
            } \
            _Pragma("unroll") \
            for (int _p = 0; _p < 4; _p++) { \
                int _r = ldr + _p * 64; \
                cp_async16(st + 16384 + SW128(_r * 128 + ldc * 16), \
                           Bq + (size_t)(n0 + _r) * K + _k0 + ldc * 8); \
            } \
        } \
        CP_COMMIT(); \
    } while (0)

    float d[2][8][4];
#pragma unroll
    for (int mi = 0; mi < 2; mi++)
#pragma unroll
        for (int ni = 0; ni < 8; ni++)
#pragma unroll
            for (int q = 0; q < 4; q++) d[mi][ni][q] = 0.f;

    const int aRow = warp_m * 32 + (lane & 15);
    const int aColB = (lane >> 4) * 16;
    const int bRow = warp_n * 64 + (lane & 7) + (lane >> 4) * 8;
    const int bColB = ((lane >> 3) & 1) * 16;

    G_LOAD(0);
    G_LOAD(1);

    for (int i = 0; i < NKT; i++) {
        CP_WAIT_1();
        __syncthreads();
        G_LOAD(i + 2);

        const uint32_t stA = sb + (i % 3) * GSTAGE_BYTES;
        const uint32_t stB = stA + 16384;
#pragma unroll
        for (int ks = 0; ks < 4; ks++) {
            const int kb = ks * 32;
            uint32_t a[2][4];
#pragma unroll
            for (int mi = 0; mi < 2; mi++)
                ldsm_x4(stA + SW128((aRow + mi * 16) * 128 + kb + aColB),
                        a[mi][0], a[mi][1], a[mi][2], a[mi][3]);
            uint32_t b[8][2];
#pragma unroll
            for (int np = 0; np < 4; np++) {
                uint32_t r0, r1, r2, r3;
                ldsm_x4(stB + SW128((bRow + np * 16) * 128 + kb + bColB),
                        r0, r1, r2, r3);
                b[np * 2][0] = r0; b[np * 2][1] = r1;
                b[np * 2 + 1][0] = r2; b[np * 2 + 1][1] = r3;
            }
#pragma unroll
            for (int mi = 0; mi < 2; mi++)
#pragma unroll
                for (int ni = 0; ni < 8; ni++)
                    mma16816(d[mi][ni], a[mi], b[ni]);
        }
    }

    const int qrow = lane >> 2;
    const int qcol = (lane & 3) * 2;
#pragma unroll
    for (int mi = 0; mi < 2; mi++) {
#pragma unroll
        for (int ni = 0; ni < 8; ni++) {
            const int col = n0 + warp_n * 64 + ni * 8 + qcol;
            const int row = m0 + warp_m * 32 + mi * 16 + qrow;
            const float b0 = bias[col], b1 = bias[col + 1];
            float v00 = d[mi][ni][0] + b0, v01 = d[mi][ni][1] + b1;
            float v10 = d[mi][ni][2] + b0, v11 = d[mi][ni][3] + b1;
            if (OUT_BF16) {
                __nv_bfloat16* C = (__nv_bfloat16*)Cout;
                __nv_bfloat162 p0 = __floats2bfloat162_rn(v00, v01);
                __nv_bfloat162 p1 = __floats2bfloat162_rn(v10, v11);
                *(__nv_bfloat162*)(C + (size_t)row * N + col) = p0;
                *(__nv_bfloat162*)(C + (size_t)(row + 8) * N + col) = p1;
            } else {
                float* C = (float*)Cout;
                *(float2*)(C + (size_t)row * N + col) = make_float2(v00, v01);
                *(float2*)(C + (size_t)(row + 8) * N + col) = make_float2(v10, v11);
            }
        }
    }
}

// ================= fused fp32 -> bf16 conversion (all tensors, 1 launch) ====
// Segments (2048 elems per block):
//   x      : blocks [0, 8192)
//   W_e2n  : [8192, 16384)
//   W_ih_f : [16384, 20480)
//   W_ih_b : [20480, 24576)
//   W_hh_f : [24576, 25088)
//   W_hh_b : [25088, 25600)
#define CVT_BLOCKS 25600
__global__ void __launch_bounds__(256)
cvt_all(const float* __restrict__ x, const float* __restrict__ we2n,
        const float* __restrict__ wihf, const float* __restrict__ wihb,
        const float* __restrict__ whhf, const float* __restrict__ whhb)
{
    int bid = blockIdx.x;
    const float* src;
    __nv_bfloat16* dst;
    if (bid < 8192)       { src = x;    dst = g_xbf; }
    else if (bid < 16384) { src = we2n; dst = g_we2n_bf; bid -= 8192; }
    else if (bid < 20480) { src = wihf; dst = g_wihf_bf; bid -= 16384; }
    else if (bid < 24576) { src = wihb; dst = g_wihb_bf; bid -= 20480; }
    else if (bid < 25088) { src = whhf; dst = g_whhf_bf; bid -= 24576; }
    else                  { src = whhb; dst = g_whhb_bf; bid -= 25088; }

    size_t base = ((size_t)bid * 256 + threadIdx.x) * 8;
    float4 a = *(const float4*)(src + base);
    float4 b = *(const float4*)(src + base + 4);
    union { __nv_bfloat16 h[8]; uint4 v; } u;
    u.h[0] = __float2bfloat16(a.x); u.h[1] = __float2bfloat16(a.y);
    u.h[2] = __float2bfloat16(a.z); u.h[3] = __float2bfloat16(a.w);
    u.h[4] = __float2bfloat16(b.x); u.h[5] = __float2bfloat16(b.y);
    u.h[6] = __float2bfloat16(b.z); u.h[7] = __float2bfloat16(b.w);
    *(uint4*)(dst + base) = u.v;
}

// ---------------- per-direction grid barrier (64 CTAs each) -----------------
__device__ __forceinline__ void grid_barrier_dir(int dir) {
    __syncthreads();
    if (threadIdx.x == 0) {
        unsigned gen = g_gen2[dir];
        __threadfence();
        if (atomicAdd(&g_bar2[dir], 1u) == 63u) {
            g_bar2[dir] = 0u;
            __threadfence();
            g_gen2[dir] = gen + 1u;
        } else {
            while (g_gen2[dir] == gen) { }
            __threadfence();
        }
    }
    __syncthreads();
}

// ---------------- persistent bidirectional LSTM (HMMA recurrence) -----------
#define HROWB 1040
#define LSTM_W_BYTES  (32 * HROWB)
#define LSTM_H_BYTES  (32 * HROWB)
#define LSTM_PSUM_BYTES (8 * 32 * 33 * 4)
#define LSTM_GPRE_BYTES (32 * 33 * 4)
#define LSTM_C_BYTES  (32 * 8 * 4)
#define LSTM_XGS_BYTES (32 * 4 * 8 * 2)     // bf16 xg tile for current step
#define LSTM_SMEM_BYTES (LSTM_W_BYTES + LSTM_H_BYTES + LSTM_PSUM_BYTES + \
                         LSTM_GPRE_BYTES + LSTM_C_BYTES + LSTM_XGS_BYTES)

__global__ void __launch_bounds__(256, 1)
lstm_kernel(const __nv_bfloat16* __restrict__ W_hh_f_bf,
            const __nv_bfloat16* __restrict__ W_hh_b_bf)
{
    extern __shared__ __align__(1024) char smc[];
    __nv_bfloat16* Wsh = (__nv_bfloat16*)smc;
    __nv_bfloat16* hsh = (__nv_bfloat16*)(smc + LSTM_W_BYTES);
    float* psum = (float*)(smc + LSTM_W_BYTES + LSTM_H_BYTES);
    float* gpre = psum + 8 * 32 * 33;
    float* csh  = gpre + 32 * 33;
    __nv_bfloat16* xgs = (__nv_bfloat16*)(csh + 32 * 8);   // [32][4][8]
    const uint32_t WshU = smem_to_u32(Wsh);
    const uint32_t hshU = smem_to_u32(hsh);
    const uint32_t xgsU = smem_to_u32(xgs);

    const int tid   = threadIdx.x;
    const int lane  = tid & 31;
    const int ks    = tid >> 5;
    const int dir   = blockIdx.x >> 6;
    const int chunk = blockIdx.x & 63;
    const int j0    = chunk * 8;
    const __nv_bfloat16* xg = dir ? g_xgb_bf : g_xgf_bf;
    const __nv_bfloat16* Whh = dir ? W_hh_b_bf : W_hh_f_bf;
    float* hs        = dir ? g_hb : g_hf;

    for (int v = tid; v < 32 * 64; v += 256) {
        int m = v >> 6, c = v & 63;
        int grow = ((m >> 3) << 9) + j0 + (m & 7);
        uint4 w = *(const uint4*)(Whh + (size_t)grow * Hn + c * 8);
        *(uint4*)((char*)Wsh + m * HROWB + c * 16) = w;
    }
    {
        int b = tid >> 3, jj = tid & 7;
        csh[b * 8 + jj] = 0.f;
        g_hping_bf[dir][0][b * Hn + j0 + jj] = __float2bfloat16(0.f);
    }
    __syncthreads();

    uint32_t afr[2][4][4];
    {
        const int aRow = lane & 15;
        const int aColB = ks * 128 + (lane >> 4) * 16;
#pragma unroll
        for (int mi = 0; mi < 2; mi++)
#pragma unroll
            for (int kk = 0; kk < 4; kk++)
                ldsm_x4(WshU + (mi * 16 + aRow) * HROWB + aColB + kk * 32,
                        afr[mi][kk][0], afr[mi][kk][1], afr[mi][kk][2], afr[mi][kk][3]);
    }
    grid_barrier_dir(dir);

    const int bRowBase = (lane & 7) + ((lane >> 4) << 3);
    const int bColB = ks * 128 + (((lane >> 3) & 1) << 4);
    const int qrow = lane >> 2;
    const int qcol = (lane & 3) * 2;
    // xg prefetch mapping: tid<128 -> (b = tid>>2, gate = tid&3), 16B (8 bf16)
    const int pfB = tid >> 2;
    const int pfG = tid & 3;

    for (int t = 0; t < Tn; t++) {
        const int p = t & 1;
        const int tact = dir ? (Tn - 1 - t) : t;

        // group A: stage h (bf16, 32x512) into padded smem rows
        const __nv_bfloat16* hg = g_hping_bf[dir][p];
#pragma unroll
        for (int u = 0; u < 8; u++) {
            int idx = tid + u * 256;
            int b = idx >> 6, c = idx & 63;
            cp_async16(hshU + b * HROWB + c * 16, hg + b * Hn + c * 8);
        }
        CP_COMMIT();

        // group B: prefetch this step's xg tile (hidden behind HMMA+reduce)
        if (tid < 128) {
            cp_async16(xgsU + tid * 16,
                       xg + ((size_t)tact * Bn + pfB) * FOURH + pfG * 512 + j0);
        }
        CP_COMMIT();

        CP_WAIT_1();                 // h ready; xg still in flight
        __syncthreads();

        float d[2][4][4];
#pragma unroll
        for (int mi = 0; mi < 2; mi++)
#pragma unroll
            for (int ni = 0; ni < 4; ni++)
#pragma unroll
                for (int q = 0; q < 4; q++) d[mi][ni][q] = 0.f;

#pragma unroll
        for (int kk = 0; kk < 4; kk++) {
            uint32_t bfr[4][2];
#pragma unroll
            for (int nt = 0; nt < 2; nt++) {
                uint32_t r0, r1, r2, r3;
                ldsm_x4(hshU + (bRowBase + nt * 16) * HROWB + bColB + kk * 32,
                        r0, r1, r2, r3);
                bfr[nt * 2][0] = r0; bfr[nt * 2][1] = r1;
                bfr[nt * 2 + 1][0] = r2; bfr[nt * 2 + 1][1] = r3;
            }
#pragma unroll
            for (int mi = 0; mi < 2; mi++)
#pragma unroll
                for (int ni = 0; ni < 4; ni++)
                    mma16816(d[mi][ni], afr[mi][kk], bfr[ni]);
        }

#pragma unroll
        for (int mi = 0; mi < 2; mi++)
#pragma unroll
            for (int ni = 0; ni < 4; ni++) {
                int r = mi * 16 + qrow;
                int c = ni * 8 + qcol;
                psum[(ks * 32 + r) * 33 + c]       = d[mi][ni][0];
                psum[(ks * 32 + r) * 33 + c + 1]   = d[mi][ni][1];
                psum[(ks * 32 + r + 8) * 33 + c]     = d[mi][ni][2];
                psum[(ks * 32 + r + 8) * 33 + c + 1] = d[mi][ni][3];
            }
        __syncthreads();

#pragma unroll
        for (int u = 0; u < 4; u++) {
            int idx = tid + u * 256;
            int r = idx >> 5, b = idx & 31;
            float s = 0.f;
#pragma unroll
            for (int kk = 0; kk < 8; kk++) s += psum[(kk * 32 + r) * 33 + b];
            gpre[r * 33 + b] = s;
        }
        CP_WAIT_0();                 // xg landed
        __syncthreads();

        {
            int b = tid >> 3, jj = tid & 7;
            const __nv_bfloat16* xr = xgs + (b * 4) * 8 + jj;
            float gi = gpre[(jj) * 33 + b]      + __bfloat162float(xr[0]);
            float gf = gpre[(8 + jj) * 33 + b]  + __bfloat162float(xr[8]);
            float gg = gpre[(16 + jj) * 33 + b] + __bfloat162float(xr[16]);
            float go = gpre[(24 + jj) * 33 + b] + __bfloat162float(xr[24]);
            float iv = 1.f / (1.f + expf(-gi));
            float fv = 1.f / (1.f + expf(-gf));
            float gv = tanhf(gg);
            float ov = 1.f / (1.f + expf(-go));
            float c = fv * csh[b * 8 + jj] + iv * gv;
            csh[b * 8 + jj] = c;
            float h = ov * tanhf(c);
            g_hping_bf[dir][p ^ 1][b * Hn + j0 + jj] = __float2bfloat16(h);
            hs[((size_t)tact * Bn + b) * Hn + j0 + jj] = h;
        }
        grid_barrier_dir(dir);
    }
}

// ---------------- feats: warp per (t,b) -------------------------------------
__global__ void __launch_bounds__(128)
feats_kernel(const float* __restrict__ W_lin, const float* __restrict__ b_lin)
{
    int warp = threadIdx.x >> 5, lane = threadIdx.x & 31;
    int idx = blockIdx.x * 4 + warp;
    int t = idx >> 5, b = idx & 31;
    const float* hfp = g_hf + (size_t)idx * Hn;
    const float* hbp = g_hb + (size_t)idx * Hn;

    float hreg[16], hbreg[16];
#pragma unroll
    for (int i = 0; i < 16; i++) {
        hreg[i]  = hfp[lane + 32 * i];
        hbreg[i] = hbp[lane + 32 * i];
    }
    for (int k = 0; k < Kc; k++) {
        const float* wl = W_lin + k * (2 * Hn);
        float s = 0.f;
#pragma unroll
        for (int i = 0; i < 16; i++) {
            s += hreg[i]  * wl[lane + 32 * i];
            s += hbreg[i] * wl[512 + lane + 32 * i];
        }
#pragma unroll
        for (int o = 16; o; o >>= 1) s += __shfl_xor_sync(0xffffffffu, s, o);
        if (lane == 0)
            g_feats[((size_t)b * Tn + t) * Kc + k] = s + b_lin[k];
    }
}

// ---------------- CRF: warp per batch ---------------------------------------
__global__ void __launch_bounds__(32)
crf_kernel(const int* __restrict__ tags, const float* __restrict__ trans,
           float* __restrict__ out)
{
    int b = blockIdx.x, lane = threadIdx.x;
    float tr[Kc];
#pragma unroll
    for (int j = 0; j < Kc; j++)
        tr[j] = (lane < Kc) ? trans[lane * Kc + j] : 0.f;

    float alpha = (lane == START_TAG) ? 0.f : -10000.f;
    const float* fb = g_feats + (size_t)b * Tn * Kc;

    for (int t = 0; t < Tn; t++) {
        float v[Kc];
#pragma unroll
        for (int j = 0; j < Kc; j++)
            v[j] = __shfl_sync(0xffffffffu, alpha, j) + tr[j];
        float m = v[0];
#pragma unroll
        for (int j = 1; j < Kc; j++) m = fmaxf(m, v[j]);
        float s = 0.f;
#pragma unroll
        for (int j = 0; j < Kc; j++) s += expf(v[j] - m);
        float e = (lane < Kc) ? fb[t * Kc + lane] : 0.f;
        alpha = m + logf(s) + e;
        if (lane >= Kc) alpha = -3.4e38f;
    }

    float v = (lane < Kc) ? alpha + trans[STOP_TAG * Kc + lane] : -3.4e38f;
    float m = v;
#pragma unroll
    for (int o = 16; o; o >>= 1) m = fmaxf(m, __shfl_xor_sync(0xffffffffu, m, o));
    float se = (lane < Kc) ? expf(v - m) : 0.f;
#pragma unroll
    for (int o = 16; o; o >>= 1) se += __shfl_xor_sync(0xffffffffu, se, o);
    float logZ = m + logf(se);

    const int* tg = tags + b * Tn;
    float ts = 0.f, es = 0.f;
    for (int t = lane; t < Tn; t += 32) {
        int nxt = tg[t];
        int prev = (t == 0) ? START_TAG : tg[t - 1];
        ts += trans[nxt * Kc + prev];
        es += fb[t * Kc + nxt];
    }
    if (lane == 0) ts += trans[STOP_TAG * Kc + tg[Tn - 1]];
#pragma unroll
    for (int o = 16; o; o >>= 1) {
        ts += __shfl_xor_sync(0xffffffffu, ts, o);
        es += __shfl_xor_sync(0xffffffffu, es, o);
    }
    if (lane == 0) out[b] = logZ - (ts + es);
}

// ---------------- launch -----------------------------------------------------
extern "C" void kernel_launch(void* const* d_in, const int* in_sizes, int n_in,
                              void* d_out, int out_size)
{
    const float* x      = (const float*)d_in[0];
    const int*   tags   = (const int*)d_in[1];
    const float* W_e2n  = (const float*)d_in[2];
    const float* b_e2n  = (const float*)d_in[3];
    const float* W_ih_f = (const float*)d_in[4];
    const float* W_hh_f = (const float*)d_in[5];
    const float* b_f    = (const float*)d_in[6];
    const float* W_ih_b = (const float*)d_in[7];
    const float* W_hh_b = (const float*)d_in[8];
    const float* b_b    = (const float*)d_in[9];
    const float* W_lin  = (const float*)d_in[10];
    const float* b_lin  = (const float*)d_in[11];
    const float* trans  = (const float*)d_in[12];
    float* out = (float*)d_out;

    __nv_bfloat16 *xbf, *we2nbf, *xnbf, *wihfbf, *wihbbf, *whhfbf, *whhbbf;
    __nv_bfloat16 *xgf, *xgb;
    cudaGetSymbolAddress((void**)&xbf,    g_xbf);
    cudaGetSymbolAddress((void**)&we2nbf, g_we2n_bf);
    cudaGetSymbolAddress((void**)&xnbf,   g_xnbf);
    cudaGetSymbolAddress((void**)&wihfbf, g_wihf_bf);
    cudaGetSymbolAddress((void**)&wihbbf, g_wihb_bf);
    cudaGetSymbolAddress((void**)&whhfbf, g_whhf_bf);
    cudaGetSymbolAddress((void**)&whhbbf, g_whhb_bf);
    cudaGetSymbolAddress((void**)&xgf,    g_xgf_bf);
    cudaGetSymbolAddress((void**)&xgb,    g_xgb_bf);

    cudaFuncSetAttribute(lstm_kernel,
                         cudaFuncAttributeMaxDynamicSharedMemorySize,
                         LSTM_SMEM_BYTES);
    cudaFuncSetAttribute((const void*)gemm_hmma<true, false>,
                         cudaFuncAttributeMaxDynamicSharedMemorySize,
                         GEMM_SMEM_BYTES);
    cudaFuncSetAttribute((const void*)gemm_hmma<true, true>,
                         cudaFuncAttributeMaxDynamicSharedMemorySize,
                         GEMM_SMEM_BYTES);

    // 0) all fp32 -> bf16 conversions in one launch
    cvt_all<<<CVT_BLOCKS, 256>>>(x, W_e2n, W_ih_f, W_ih_b, W_hh_f, W_hh_b);

    // 1) xn = x @ W_e2n^T + b_e2n  (bf16 out)
    {
        dim3 grid(En / 256, TB / 128);
        gemm_hmma<true, false><<<grid, 512, GEMM_SMEM_BYTES>>>(
            xbf, we2nbf, nullptr, b_e2n, nullptr, xnbf, nullptr, TB, En, En, 0);
    }
    // 2) xg_f / xg_b = xn @ W_ih^T + b  (bf16 out; one fused launch)
    {
        dim3 grid(2 * (FOURH / 256), TB / 128);
        gemm_hmma<true, true><<<grid, 512, GEMM_SMEM_BYTES>>>(
            xnbf, wihfbf, wihbbf, b_f, b_b, xgf, xgb, TB, FOURH, En, FOURH / 256);
    }
    // 3) bidirectional LSTM scan (HMMA recurrence, per-dir barriers,
    //    xg prefetch overlapped)
    lstm_kernel<<<128, 256, LSTM_SMEM_BYTES>>>(whhfbf, whhbbf);

    // 4) feats
    feats_kernel<<<TB / 4, 128>>>(W_lin, b_lin);

    // 5) CRF
    crf_kernel<<<Bn, 32>>>(tags, trans, out);
}

// round 8
// speedup vs baseline: 5.0773x; 1.0366x over previous
#include <cuda_runtime.h>
#include <cuda_bf16.h>
#include <math.h>
#include <stdint.h>

// ---------------- problem constants ----------------
#define Tn 128
#define Bn 32
#define En 4096
#define Hn 512
#define FOURH 2048
#define TB 4096          // T*B
#define Kc 20
#define START_TAG 18
#define STOP_TAG 19

// ---------------- scratch (device globals; allocation-free) ----------------
__device__ __align__(256) __nv_bfloat16 g_xbf[(size_t)TB * En];
__device__ __align__(256) __nv_bfloat16 g_we2n_bf[(size_t)En * En];
__device__ __align__(256) __nv_bfloat16 g_xnbf[(size_t)TB * En];
__device__ __align__(256) __nv_bfloat16 g_wihf_bf[(size_t)FOURH * En];
__device__ __align__(256) __nv_bfloat16 g_wihb_bf[(size_t)FOURH * En];
__device__ __align__(256) __nv_bfloat16 g_whhf_bf[(size_t)FOURH * Hn];
__device__ __align__(256) __nv_bfloat16 g_whhb_bf[(size_t)FOURH * Hn];
__device__ __align__(256) __nv_bfloat16 g_xgf_bf[(size_t)TB * FOURH];
__device__ __align__(256) __nv_bfloat16 g_xgb_bf[(size_t)TB * FOURH];
__device__ float g_hf[(size_t)TB * Hn];
__device__ float g_hb[(size_t)TB * Hn];
__device__ __align__(256) __nv_bfloat16 g_hping_bf[2][2][Bn * Hn];
__device__ float g_feats[(size_t)Bn * Tn * Kc];

// setup barrier (atomic, used once) + per-step flag barrier (128B-strided)
__device__ unsigned g_bar2[2] = {0u, 0u};
__device__ volatile unsigned g_gen2[2] = {0u, 0u};
__device__ __align__(256) unsigned g_flags[2][64 * 32];   // flag at [chunk*32]

// ================= helpers ===================================================
__device__ __forceinline__ uint32_t smem_to_u32(const void* p) {
    uint32_t a;
    asm("{ .reg .u64 t; cvta.to.shared.u64 t, %1; cvt.u32.u64 %0, t; }"
        : "=r"(a) : "l"(p));
    return a;
}
#define SW128(o) ((o) ^ (((o) >> 3) & 0x70))

__device__ __forceinline__ void cp_async16(uint32_t dst, const void* src) {
    asm volatile("cp.async.cg.shared.global [%0], [%1], 16;" :: "r"(dst), "l"(src));
}
#define CP_COMMIT() asm volatile("cp.async.commit_group;" ::: "memory")
#define CP_WAIT_1() asm volatile("cp.async.wait_group 1;" ::: "memory")
#define CP_WAIT_0() asm volatile("cp.async.wait_group 0;" ::: "memory")

__device__ __forceinline__ void ldsm_x4(uint32_t addr, uint32_t& r0, uint32_t& r1,
                                        uint32_t& r2, uint32_t& r3) {
    asm volatile("ldmatrix.sync.aligned.m8n8.x4.shared.b16 {%0,%1,%2,%3}, [%4];"
                 : "=r"(r0), "=r"(r1), "=r"(r2), "=r"(r3) : "r"(addr));
}

__device__ __forceinline__ void mma16816(float* d, const uint32_t* a, const uint32_t* b) {
    asm volatile(
        "mma.sync.aligned.m16n8k16.row.col.f32.bf16.bf16.f32 "
        "{%0,%1,%2,%3}, {%4,%5,%6,%7}, {%8,%9}, {%0,%1,%2,%3};"
        : "+f"(d[0]), "+f"(d[1]), "+f"(d[2]), "+f"(d[3])
        : "r"(a[0]), "r"(a[1]), "r"(a[2]), "r"(a[3]), "r"(b[0]), "r"(b[1]));
}

// ================= HMMA GEMM: C[M,N] = A[M,K]bf16 @ B[N,K]bf16^T + bias ======
#define GSTAGE_BYTES 49152                  // A 16KB + B 32KB
#define GEMM_SMEM_BYTES (3 * GSTAGE_BYTES)  // 144KB

template <bool OUT_BF16, bool DUAL>
__global__ void __launch_bounds__(512)
gemm_hmma(const __nv_bfloat16* __restrict__ Aq, const __nv_bfloat16* __restrict__ Bq0,
          const __nv_bfloat16* __restrict__ Bq1,
          const float* __restrict__ bias0, const float* __restrict__ bias1,
          void* __restrict__ Cout0, void* __restrict__ Cout1,
          int M, int N, int K, int nbx)
{
    extern __shared__ __align__(1024) char smem[];
    const uint32_t sb = smem_to_u32(smem);

    const int tid = threadIdx.x;
    const int wid = tid >> 5;
    const int lane = tid & 31;
    const int warp_m = wid & 3;
    const int warp_n = wid >> 2;            // 0..3
    int bx = blockIdx.x;
    const __nv_bfloat16* Bq = Bq0;
    const float* bias = bias0;
    void* Cout = Cout0;
    if (DUAL && bx >= nbx) {
        bx -= nbx; Bq = Bq1; bias = bias1; Cout = Cout1;
    }
    const int m0 = blockIdx.y * 128;
    const int n0 = bx * 256;
    const int NKT = K / 64;

    const int ldr = tid >> 3;               // 0..63
    const int ldc = tid & 7;

#define G_LOAD(kt) do { \
        if ((kt) < NKT) { \
            const uint32_t st = sb + ((kt) % 3) * GSTAGE_BYTES; \
            int _k0 = (kt) * 64; \
            _Pragma("unroll") \
            for (int _p = 0; _p < 2; _p++) { \
                int _r = ldr + _p * 64; \
                cp_async16(st + SW128(_r * 128 + ldc * 16), \
                           Aq + (size_t)(m0 + _r) * K + _k0 + ldc * 8); \
            } \
            _Pragma("unroll") \
            for (int _p = 0; _p < 4; _p++) { \
                int _r = ldr + _p * 64; \
                cp_async16(st + 16384 + SW128(_r * 128 + ldc * 16), \
                           Bq + (size_t)(n0 + _r) * K + _k0 + ldc * 8); \
            } \
        } \
        CP_COMMIT(); \
    } while (0)

    float d[2][8][4];
#pragma unroll
    for (int mi = 0; mi < 2; mi++)
#pragma unroll
        for (int ni = 0; ni < 8; ni++)
#pragma unroll
            for (int q = 0; q < 4; q++) d[mi][ni][q] = 0.f;

    const int aRow = warp_m * 32 + (lane & 15);
    const int aColB = (lane >> 4) * 16;
    const int bRow = warp_n * 64 + (lane & 7) + (lane >> 4) * 8;
    const int bColB = ((lane >> 3) & 1) * 16;

    G_LOAD(0);
    G_LOAD(1);

    for (int i = 0; i < NKT; i++) {
        CP_WAIT_1();
        __syncthreads();
        G_LOAD(i + 2);

        const uint32_t stA = sb + (i % 3) * GSTAGE_BYTES;
        const uint32_t stB = stA + 16384;
#pragma unroll
        for (int ks = 0; ks < 4; ks++) {
            const int kb = ks * 32;
            uint32_t a[2][4];
#pragma unroll
            for (int mi = 0; mi < 2; mi++)
                ldsm_x4(stA + SW128((aRow + mi * 16) * 128 + kb + aColB),
                        a[mi][0], a[mi][1], a[mi][2], a[mi][3]);
            uint32_t b[8][2];
#pragma unroll
            for (int np = 0; np < 4; np++) {
                uint32_t r0, r1, r2, r3;
                ldsm_x4(stB + SW128((bRow + np * 16) * 128 + kb + bColB),
                        r0, r1, r2, r3);
                b[np * 2][0] = r0; b[np * 2][1] = r1;
                b[np * 2 + 1][0] = r2; b[np * 2 + 1][1] = r3;
            }
#pragma unroll
            for (int mi = 0; mi < 2; mi++)
#pragma unroll
                for (int ni = 0; ni < 8; ni++)
                    mma16816(d[mi][ni], a[mi], b[ni]);
        }
    }

    const int qrow = lane >> 2;
    const int qcol = (lane & 3) * 2;
#pragma unroll
    for (int mi = 0; mi < 2; mi++) {
#pragma unroll
        for (int ni = 0; ni < 8; ni++) {
            const int col = n0 + warp_n * 64 + ni * 8 + qcol;
            const int row = m0 + warp_m * 32 + mi * 16 + qrow;
            const float b0 = bias[col], b1 = bias[col + 1];
            float v00 = d[mi][ni][0] + b0, v01 = d[mi][ni][1] + b1;
            float v10 = d[mi][ni][2] + b0, v11 = d[mi][ni][3] + b1;
            if (OUT_BF16) {
                __nv_bfloat16* C = (__nv_bfloat16*)Cout;
                __nv_bfloat162 p0 = __floats2bfloat162_rn(v00, v01);
                __nv_bfloat162 p1 = __floats2bfloat162_rn(v10, v11);
                *(__nv_bfloat162*)(C + (size_t)row * N + col) = p0;
                *(__nv_bfloat162*)(C + (size_t)(row + 8) * N + col) = p1;
            } else {
                float* C = (float*)Cout;
                *(float2*)(C + (size_t)row * N + col) = make_float2(v00, v01);
                *(float2*)(C + (size_t)(row + 8) * N + col) = make_float2(v10, v11);
            }
        }
    }
}

// ================= fused fp32 -> bf16 conversion (all tensors, 1 launch) ====
#define CVT_BLOCKS 25600
__global__ void __launch_bounds__(256)
cvt_all(const float* __restrict__ x, const float* __restrict__ we2n,
        const float* __restrict__ wihf, const float* __restrict__ wihb,
        const float* __restrict__ whhf, const float* __restrict__ whhb)
{
    int bid = blockIdx.x;
    const float* src;
    __nv_bfloat16* dst;
    if (bid < 8192)       { src = x;    dst = g_xbf; }
    else if (bid < 16384) { src = we2n; dst = g_we2n_bf; bid -= 8192; }
    else if (bid < 20480) { src = wihf; dst = g_wihf_bf; bid -= 16384; }
    else if (bid < 24576) { src = wihb; dst = g_wihb_bf; bid -= 20480; }
    else if (bid < 25088) { src = whhf; dst = g_whhf_bf; bid -= 24576; }
    else                  { src = whhb; dst = g_whhb_bf; bid -= 25088; }

    size_t base = ((size_t)bid * 256 + threadIdx.x) * 8;
    float4 a = *(const float4*)(src + base);
    float4 b = *(const float4*)(src + base + 4);
    union { __nv_bfloat16 h[8]; uint4 v; } u;
    u.h[0] = __float2bfloat16(a.x); u.h[1] = __float2bfloat16(a.y);
    u.h[2] = __float2bfloat16(a.z); u.h[3] = __float2bfloat16(a.w);
    u.h[4] = __float2bfloat16(b.x); u.h[5] = __float2bfloat16(b.y);
    u.h[6] = __float2bfloat16(b.z); u.h[7] = __float2bfloat16(b.w);
    *(uint4*)(dst + base) = u.v;
}

// ---------------- setup barrier (atomic, once per launch) --------------------
__device__ __forceinline__ void grid_barrier_dir(int dir) {
    __syncthreads();
    if (threadIdx.x == 0) {
        unsigned gen = g_gen2[dir];
        __threadfence();
        if (atomicAdd(&g_bar2[dir], 1u) == 63u) {
            g_bar2[dir] = 0u;
            __threadfence();
            g_gen2[dir] = gen + 1u;
        } else {
            while (g_gen2[dir] == gen) { __nanosleep(64); }
            __threadfence();
        }
    }
    __syncthreads();
}

// ---------------- per-step flag barrier wait ---------------------------------
// warp 0 polls all 64 flags (128B-strided) with L2 loads + nanosleep backoff.
__device__ __forceinline__ void wait_flags(const unsigned* f, unsigned target) {
    if (threadIdx.x < 32) {
        const unsigned* p0 = f + (threadIdx.x * 2) * 32;
        const unsigned* p1 = f + (threadIdx.x * 2 + 1) * 32;
        while (true) {
            unsigned a, b;
            asm volatile("ld.global.cg.u32 %0, [%1];" : "=r"(a) : "l"(p0));
            asm volatile("ld.global.cg.u32 %0, [%1];" : "=r"(b) : "l"(p1));
            if (__all_sync(0xffffffffu, (a >= target) && (b >= target))) break;
            __nanosleep(40);
        }
        __threadfence();
    }
    __syncthreads();
}

// ---------------- persistent bidirectional LSTM (HMMA recurrence) -----------
#define HROWB 1040
#define LSTM_W_BYTES  (32 * HROWB)
#define LSTM_H_BYTES  (32 * HROWB)
#define LSTM_PSUM_BYTES (8 * 32 * 33 * 4)
#define LSTM_GPRE_BYTES (32 * 33 * 4)
#define LSTM_C_BYTES  (32 * 8 * 4)
#define LSTM_XGS_BYTES (32 * 4 * 8 * 2)
#define LSTM_SMEM_BYTES (LSTM_W_BYTES + LSTM_H_BYTES + LSTM_PSUM_BYTES + \
                         LSTM_GPRE_BYTES + LSTM_C_BYTES + LSTM_XGS_BYTES)

__global__ void __launch_bounds__(256, 1)
lstm_kernel(const __nv_bfloat16* __restrict__ W_hh_f_bf,
            const __nv_bfloat16* __restrict__ W_hh_b_bf)
{
    extern __shared__ __align__(1024) char smc[];
    __nv_bfloat16* Wsh = (__nv_bfloat16*)smc;
    __nv_bfloat16* hsh = (__nv_bfloat16*)(smc + LSTM_W_BYTES);
    float* psum = (float*)(smc + LSTM_W_BYTES + LSTM_H_BYTES);
    float* gpre = psum + 8 * 32 * 33;
    float* csh  = gpre + 32 * 33;
    __nv_bfloat16* xgs = (__nv_bfloat16*)(csh + 32 * 8);
    const uint32_t WshU = smem_to_u32(Wsh);
    const uint32_t hshU = smem_to_u32(hsh);
    const uint32_t xgsU = smem_to_u32(xgs);

    const int tid   = threadIdx.x;
    const int lane  = tid & 31;
    const int ks    = tid >> 5;
    const int dir   = blockIdx.x >> 6;
    const int chunk = blockIdx.x & 63;
    const int j0    = chunk * 8;
    const __nv_bfloat16* xg = dir ? g_xgb_bf : g_xgf_bf;
    const __nv_bfloat16* Whh = dir ? W_hh_b_bf : W_hh_f_bf;
    float* hs        = dir ? g_hb : g_hf;
    unsigned* flags  = g_flags[dir];

    for (int v = tid; v < 32 * 64; v += 256) {
        int m = v >> 6, c = v & 63;
        int grow = ((m >> 3) << 9) + j0 + (m & 7);
        uint4 w = *(const uint4*)(Whh + (size_t)grow * Hn + c * 8);
        *(uint4*)((char*)Wsh + m * HROWB + c * 16) = w;
    }
    {
        int b = tid >> 3, jj = tid & 7;
        csh[b * 8 + jj] = 0.f;
        g_hping_bf[dir][0][b * Hn + j0 + jj] = __float2bfloat16(0.f);
    }
    if (tid == 0) {
        asm volatile("st.global.cg.u32 [%0], %1;"
                     :: "l"(flags + chunk * 32), "r"(0u) : "memory");
    }
    __syncthreads();

    uint32_t afr[2][4][4];
    {
        const int aRow = lane & 15;
        const int aColB = ks * 128 + (lane >> 4) * 16;
#pragma unroll
        for (int mi = 0; mi < 2; mi++)
#pragma unroll
            for (int kk = 0; kk < 4; kk++)
                ldsm_x4(WshU + (mi * 16 + aRow) * HROWB + aColB + kk * 32,
                        afr[mi][kk][0], afr[mi][kk][1], afr[mi][kk][2], afr[mi][kk][3]);
    }
    grid_barrier_dir(dir);   // orders flag resets + h0 init across the grid

    const int bRowBase = (lane & 7) + ((lane >> 4) << 3);
    const int bColB = ks * 128 + (((lane >> 3) & 1) << 4);
    const int qrow = lane >> 2;
    const int qcol = (lane & 3) * 2;
    const int pfB = tid >> 2;
    const int pfG = tid & 3;

    for (int t = 0; t < Tn; t++) {
        const int p = t & 1;
        const int tact = dir ? (Tn - 1 - t) : t;

        // prefetch xg (h-independent) so it overlaps the flag poll
        if (tid < 128) {
            cp_async16(xgsU + tid * 16,
                       xg + ((size_t)tact * Bn + pfB) * FOURH + pfG * 512 + j0);
        }
        CP_COMMIT();

        if (t > 0) wait_flags(flags, (unsigned)t);

        // stage h (bf16, 32x512) into padded smem rows
        const __nv_bfloat16* hg = g_hping_bf[dir][p];
#pragma unroll
        for (int u = 0; u < 8; u++) {
            int idx = tid + u * 256;
            int b = idx >> 6, c = idx & 63;
            cp_async16(hshU + b * HROWB + c * 16, hg + b * Hn + c * 8);
        }
        CP_COMMIT();
        CP_WAIT_0();
        __syncthreads();

        float d[2][4][4];
#pragma unroll
        for (int mi = 0; mi < 2; mi++)
#pragma unroll
            for (int ni = 0; ni < 4; ni++)
#pragma unroll
                for (int q = 0; q < 4; q++) d[mi][ni][q] = 0.f;

#pragma unroll
        for (int kk = 0; kk < 4; kk++) {
            uint32_t bfr[4][2];
#pragma unroll
            for (int nt = 0; nt < 2; nt++) {
                uint32_t r0, r1, r2, r3;
                ldsm_x4(hshU + (bRowBase + nt * 16) * HROWB + bColB + kk * 32,
                        r0, r1, r2, r3);
                bfr[nt * 2][0] = r0; bfr[nt * 2][1] = r1;
                bfr[nt * 2 + 1][0] = r2; bfr[nt * 2 + 1][1] = r3;
            }
#pragma unroll
            for (int mi = 0; mi < 2; mi++)
#pragma unroll
                for (int ni = 0; ni < 4; ni++)
                    mma16816(d[mi][ni], afr[mi][kk], bfr[ni]);
        }

#pragma unroll
        for (int mi = 0; mi < 2; mi++)
#pragma unroll
            for (int ni = 0; ni < 4; ni++) {
                int r = mi * 16 + qrow;
                int c = ni * 8 + qcol;
                psum[(ks * 32 + r) * 33 + c]       = d[mi][ni][0];
                psum[(ks * 32 + r) * 33 + c + 1]   = d[mi][ni][1];
                psum[(ks * 32 + r + 8) * 33 + c]     = d[mi][ni][2];
                psum[(ks * 32 + r + 8) * 33 + c + 1] = d[mi][ni][3];
            }
        __syncthreads();

#pragma unroll
        for (int u = 0; u < 4; u++) {
            int idx = tid + u * 256;
            int r = idx >> 5, b = idx & 31;
            float s = 0.f;
#pragma unroll
            for (int kk = 0; kk < 8; kk++) s += psum[(kk * 32 + r) * 33 + b];
            gpre[r * 33 + b] = s;
        }
        __syncthreads();

        {
            int b = tid >> 3, jj = tid & 7;
            const __nv_bfloat16* xr = xgs + (b * 4) * 8 + jj;
            float gi = gpre[(jj) * 33 + b]      + __bfloat162float(xr[0]);
            float gf = gpre[(8 + jj) * 33 + b]  + __bfloat162float(xr[8]);
            float gg = gpre[(16 + jj) * 33 + b] + __bfloat162float(xr[16]);
            float go = gpre[(24 + jj) * 33 + b] + __bfloat162float(xr[24]);
            float iv = 1.f / (1.f + expf(-gi));
            float fv = 1.f / (1.f + expf(-gf));
            float gv = tanhf(gg);
            float ov = 1.f / (1.f + expf(-go));
            float c = fv * csh[b * 8 + jj] + iv * gv;
            csh[b * 8 + jj] = c;
            float h = ov * tanhf(c);
            g_hping_bf[dir][p ^ 1][b * Hn + j0 + jj] = __float2bfloat16(h);
            hs[((size_t)tact * Bn + b) * Hn + j0 + jj] = h;
        }
        __syncthreads();                   // all h stores issued
        if (tid == 0) {
            unsigned val = (unsigned)(t + 1);
            // release: orders the h stores before the flag becomes visible
            asm volatile("st.global.release.gpu.u32 [%0], %1;"
                         :: "l"(flags + chunk * 32), "r"(val) : "memory");
        }
    }
}

// ---------------- feats: warp per (t,b) -------------------------------------
__global__ void __launch_bounds__(128)
feats_kernel(const float* __restrict__ W_lin, const float* __restrict__ b_lin)
{
    int warp = threadIdx.x >> 5, lane = threadIdx.x & 31;
    int idx = blockIdx.x * 4 + warp;
    int t = idx >> 5, b = idx & 31;
    const float* hfp = g_hf + (size_t)idx * Hn;
    const float* hbp = g_hb + (size_t)idx * Hn;

    float hreg[16], hbreg[16];
#pragma unroll
    for (int i = 0; i < 16; i++) {
        hreg[i]  = hfp[lane + 32 * i];
        hbreg[i] = hbp[lane + 32 * i];
    }
    for (int k = 0; k < Kc; k++) {
        const float* wl = W_lin + k * (2 * Hn);
        float s = 0.f;
#pragma unroll
        for (int i = 0; i < 16; i++) {
            s += hreg[i]  * wl[lane + 32 * i];
            s += hbreg[i] * wl[512 + lane + 32 * i];
        }
#pragma unroll
        for (int o = 16; o; o >>= 1) s += __shfl_xor_sync(0xffffffffu, s, o);
        if (lane == 0)
            g_feats[((size_t)b * Tn + t) * Kc + k] = s + b_lin[k];
    }
}

// ---------------- CRF: warp per batch ---------------------------------------
__global__ void __launch_bounds__(32)
crf_kernel(const int* __restrict__ tags, const float* __restrict__ trans,
           float* __restrict__ out)
{
    int b = blockIdx.x, lane = threadIdx.x;
    float tr[Kc];
#pragma unroll
    for (int j = 0; j < Kc; j++)
        tr[j] = (lane < Kc) ? trans[lane * Kc + j] : 0.f;

    float alpha = (lane == START_TAG) ? 0.f : -10000.f;
    const float* fb = g_feats + (size_t)b * Tn * Kc;

    for (int t = 0; t < Tn; t++) {
        float v[Kc];
#pragma unroll
        for (int j = 0; j < Kc; j++)
            v[j] = __shfl_sync(0xffffffffu, alpha, j) + tr[j];
        float m = v[0];
#pragma unroll
        for (int j = 1; j < Kc; j++) m = fmaxf(m, v[j]);
        float s = 0.f;
#pragma unroll
        for (int j = 0; j < Kc; j++) s += expf(v[j] - m);
        float e = (lane < Kc) ? fb[t * Kc + lane] : 0.f;
        alpha = m + logf(s) + e;
        if (lane >= Kc) alpha = -3.4e38f;
    }

    float v = (lane < Kc) ? alpha + trans[STOP_TAG * Kc + lane] : -3.4e38f;
    float m = v;
#pragma unroll
    for (int o = 16; o; o >>= 1) m = fmaxf(m, __shfl_xor_sync(0xffffffffu, m, o));
    float se = (lane < Kc) ? expf(v - m) : 0.f;
#pragma unroll
    for (int o = 16; o; o >>= 1) se += __shfl_xor_sync(0xffffffffu, se, o);
    float logZ = m + logf(se);

    const int* tg = tags + b * Tn;
    float ts = 0.f, es = 0.f;
    for (int t = lane; t < Tn; t += 32) {
        int nxt = tg[t];
        int prev = (t == 0) ? START_TAG : tg[t - 1];
        ts += trans[nxt * Kc + prev];
        es += fb[t * Kc + nxt];
    }
    if (lane == 0) ts += trans[STOP_TAG * Kc + tg[Tn - 1]];
#pragma unroll
    for (int o = 16; o; o >>= 1) {
        ts += __shfl_xor_sync(0xffffffffu, ts, o);
        es += __shfl_xor_sync(0xffffffffu, es, o);
    }
    if (lane == 0) out[b] = logZ - (ts + es);
}

// ---------------- launch -----------------------------------------------------
extern "C" void kernel_launch(void* const* d_in, const int* in_sizes, int n_in,
                              void* d_out, int out_size)
{
    const float* x      = (const float*)d_in[0];
    const int*   tags   = (const int*)d_in[1];
    const float* W_e2n  = (const float*)d_in[2];
    const float* b_e2n  = (const float*)d_in[3];
    const float* W_ih_f = (const float*)d_in[4];
    const float* W_hh_f = (const float*)d_in[5];
    const float* b_f    = (const float*)d_in[6];
    const float* W_ih_b = (const float*)d_in[7];
    const float* W_hh_b = (const float*)d_in[8];
    const float* b_b    = (const float*)d_in[9];
    const float* W_lin  = (const float*)d_in[10];
    const float* b_lin  = (const float*)d_in[11];
    const float* trans  = (const float*)d_in[12];
    float* out = (float*)d_out;

    __nv_bfloat16 *xbf, *we2nbf, *xnbf, *wihfbf, *wihbbf, *whhfbf, *whhbbf;
    __nv_bfloat16 *xgf, *xgb;
    cudaGetSymbolAddress((void**)&xbf,    g_xbf);
    cudaGetSymbolAddress((void**)&we2nbf, g_we2n_bf);
    cudaGetSymbolAddress((void**)&xnbf,   g_xnbf);
    cudaGetSymbolAddress((void**)&wihfbf, g_wihf_bf);
    cudaGetSymbolAddress((void**)&wihbbf, g_wihb_bf);
    cudaGetSymbolAddress((void**)&whhfbf, g_whhf_bf);
    cudaGetSymbolAddress((void**)&whhbbf, g_whhb_bf);
    cudaGetSymbolAddress((void**)&xgf,    g_xgf_bf);
    cudaGetSymbolAddress((void**)&xgb,    g_xgb_bf);

    cudaFuncSetAttribute(lstm_kernel,
                         cudaFuncAttributeMaxDynamicSharedMemorySize,
                         LSTM_SMEM_BYTES);
    cudaFuncSetAttribute((const void*)gemm_hmma<true, false>,
                         cudaFuncAttributeMaxDynamicSharedMemorySize,
                         GEMM_SMEM_BYTES);
    cudaFuncSetAttribute((const void*)gemm_hmma<true, true>,
                         cudaFuncAttributeMaxDynamicSharedMemorySize,
                         GEMM_SMEM_BYTES);

    // 0) all fp32 -> bf16 conversions in one launch
    cvt_all<<<CVT_BLOCKS, 256>>>(x, W_e2n, W_ih_f, W_ih_b, W_hh_f, W_hh_b);

    // 1) xn = x @ W_e2n^T + b_e2n  (bf16 out)
    {
        dim3 grid(En / 256, TB / 128);
        gemm_hmma<true, false><<<grid, 512, GEMM_SMEM_BYTES>>>(
            xbf, we2nbf, nullptr, b_e2n, nullptr, xnbf, nullptr, TB, En, En, 0);
    }
    // 2) xg_f / xg_b = xn @ W_ih^T + b  (bf16 out; one fused launch)
    {
        dim3 grid(2 * (FOURH / 256), TB / 128);
        gemm_hmma<true, true><<<grid, 512, GEMM_SMEM_BYTES>>>(
            xnbf, wihfbf, wihbbf, b_f, b_b, xgf, xgb, TB, FOURH, En, FOURH / 256);
    }
    // 3) bidirectional LSTM scan (flag-barrier pipeline, backoff poll)
    lstm_kernel<<<128, 256, LSTM_SMEM_BYTES>>>(whhfbf, whhbbf);

    // 4) feats
    feats_kernel<<<TB / 4, 128>>>(W_lin, b_lin);

    // 5) CRF
    crf_kernel<<<Bn, 32>>>(tags, trans, out);
}